// round 3
// baseline (speedup 1.0000x reference)
#include <cuda_runtime.h>
#include <cuda_bf16.h>
#include <cstdint>
#include <cstddef>

#define BB 4
#define SS 1024
#define HIDD 1024
#define HH 16
#define DD 64

// scratch: q,k,v in [B,H,S,D] layout
__device__ float g_q[BB*HH*SS*DD];
__device__ float g_k[BB*HH*SS*DD];
__device__ float g_v[BB*HH*SS*DD];

__device__ __forceinline__ uint32_t smem_u32(const void* p) {
    uint32_t a;
    asm("{ .reg .u64 t; cvta.to.shared.u64 t, %1; cvt.u32.u64 %0, t; }" : "=r"(a) : "l"(p));
    return a;
}

__device__ __forceinline__ void ldsm_x4(uint32_t* r, uint32_t addr) {
    asm volatile("ldmatrix.sync.aligned.m8n8.x4.shared.b16 {%0,%1,%2,%3}, [%4];"
        : "=r"(r[0]), "=r"(r[1]), "=r"(r[2]), "=r"(r[3]) : "r"(addr));
}

__device__ __forceinline__ void mma16816(float* c, const uint32_t* a, const uint32_t* b) {
    asm volatile(
        "mma.sync.aligned.m16n8k16.row.col.f32.bf16.bf16.f32 "
        "{%0,%1,%2,%3}, {%4,%5,%6,%7}, {%8,%9}, {%0,%1,%2,%3};"
        : "+f"(c[0]), "+f"(c[1]), "+f"(c[2]), "+f"(c[3])
        : "r"(a[0]), "r"(a[1]), "r"(a[2]), "r"(a[3]), "r"(b[0]), "r"(b[1]));
}

// ---------------------------------------------------------------------------
// QKV GEMM on tensor cores (warp mma.sync, bf16 split-precision).
// C = A @ W + b, A = hidden [4096,1024], W [1024,1024] (x3 concat).
// CTA tile 128x128, BK=32. 8 warps in 4(m) x 2(n), each 32x64.
// grid (32, 24): x = m-tile, y = n-tile over [Wq|Wk|Wv].
// Output written in [B,H,S,D] layout with bias.
// ---------------------------------------------------------------------------
#define APITCH 40   // bf16 elems per smem row (80B: 16B-aligned, ldmatrix conflict-free)

__global__ __launch_bounds__(256, 2) void qkv_tc_kernel(
    const float* __restrict__ A,
    const float* __restrict__ Wq, const float* __restrict__ bq,
    const float* __restrict__ Wk, const float* __restrict__ bk,
    const float* __restrict__ Wv, const float* __restrict__ bv)
{
    __shared__ __align__(16) __nv_bfloat16 sAh[128 * APITCH];
    __shared__ __align__(16) __nv_bfloat16 sAl[128 * APITCH];
    __shared__ __align__(16) __nv_bfloat16 sBh[128 * APITCH];
    __shared__ __align__(16) __nv_bfloat16 sBl[128 * APITCH];

    int tid  = threadIdx.x;
    int wid  = tid >> 5;
    int lane = tid & 31;
    int wm = wid & 3;      // m-quadrant (32 rows)
    int wn = wid >> 2;     // n-half (64 cols)

    int m0  = blockIdx.x * 128;
    int ng0 = blockIdx.y * 128;       // col in [0, 3072)
    int sel = ng0 >> 10;              // 0=q, 1=k, 2=v
    int n0  = ng0 & 1023;

    const float* W    = (sel == 0) ? Wq : (sel == 1) ? Wk : Wv;
    const float* bias = (sel == 0) ? bq : (sel == 1) ? bk : bv;
    float* outm       = (sel == 0) ? g_q : (sel == 1) ? g_k : g_v;

    uint32_t baseAh = smem_u32(sAh), baseAl = smem_u32(sAl);
    uint32_t baseBh = smem_u32(sBh), baseBl = smem_u32(sBl);

    float acc[2][8][4] = {};

    // ldmatrix source addresses (constant across stages except kk)
    int a_row = (lane & 15);
    int a_kof = (lane >> 4) * 8;
    int b_nof = (lane & 7) | ((lane >> 4) << 3);
    int b_kof = ((lane >> 3) & 1) * 8;

    for (int s = 0; s < 32; s++) {
        int k0 = s * 32;
        __syncthreads();

        // ---- A tile: 128 rows x 32 k, fp32 -> bf16 hi/lo ----
        #pragma unroll
        for (int p = 0; p < 4; p++) {
            int idx = tid + p * 256;
            int row = idx >> 3;            // 8 float4 per row
            int kq  = (idx & 7) * 4;
            float4 a4 = *(const float4*)&A[(size_t)(m0 + row) * HIDD + k0 + kq];
            float2 p01 = make_float2(a4.x, a4.y);
            float2 p23 = make_float2(a4.z, a4.w);
            __nv_bfloat162 h01 = __float22bfloat162_rn(p01);
            __nv_bfloat162 h23 = __float22bfloat162_rn(p23);
            float2 r01 = make_float2(a4.x - __bfloat162float(h01.x),
                                     a4.y - __bfloat162float(h01.y));
            float2 r23 = make_float2(a4.z - __bfloat162float(h23.x),
                                     a4.w - __bfloat162float(h23.y));
            __nv_bfloat162 l01 = __float22bfloat162_rn(r01);
            __nv_bfloat162 l23 = __float22bfloat162_rn(r23);
            int off = row * APITCH + kq;
            *(uint2*)&sAh[off] = make_uint2(*(uint32_t*)&h01, *(uint32_t*)&h23);
            *(uint2*)&sAl[off] = make_uint2(*(uint32_t*)&l01, *(uint32_t*)&l23);
        }
        // ---- B tile: W[k][n] -> sB[n][k] (transposed), 32 k x 128 n ----
        #pragma unroll
        for (int p = 0; p < 4; p++) {
            int idx = tid + p * 256;
            int kk = idx >> 5;             // 32 float4 per k-row
            int n  = (idx & 31) * 4;
            float4 w4 = *(const float4*)&W[(size_t)(k0 + kk) * HIDD + n0 + n];
            float wv[4] = {w4.x, w4.y, w4.z, w4.w};
            #pragma unroll
            for (int j = 0; j < 4; j++) {
                __nv_bfloat16 hh = __float2bfloat16_rn(wv[j]);
                __nv_bfloat16 ll = __float2bfloat16_rn(wv[j] - __bfloat162float(hh));
                sBh[(n + j) * APITCH + kk] = hh;
                sBl[(n + j) * APITCH + kk] = ll;
            }
        }
        __syncthreads();

        // ---- compute: 2 k-steps of m16n8k16 ----
        #pragma unroll
        for (int kk = 0; kk < 32; kk += 16) {
            uint32_t ah[2][4], al[2][4], bh[16], bl[16];
            #pragma unroll
            for (int mt = 0; mt < 2; mt++) {
                int off = ((wm * 32 + mt * 16 + a_row) * APITCH + kk + a_kof) * 2;
                ldsm_x4(ah[mt], baseAh + off);
                ldsm_x4(al[mt], baseAl + off);
            }
            #pragma unroll
            for (int np = 0; np < 4; np++) {
                int off = ((wn * 64 + np * 16 + b_nof) * APITCH + kk + b_kof) * 2;
                ldsm_x4(&bh[np * 4], baseBh + off);
                ldsm_x4(&bl[np * 4], baseBl + off);
            }
            #pragma unroll
            for (int mt = 0; mt < 2; mt++)
                #pragma unroll
                for (int nt = 0; nt < 8; nt++) {
                    mma16816(acc[mt][nt], ah[mt], &bh[nt * 2]);
                    mma16816(acc[mt][nt], ah[mt], &bl[nt * 2]);
                    mma16816(acc[mt][nt], al[mt], &bh[nt * 2]);
                }
        }
    }

    // ---- epilogue: bias + store to [B,H,S,D] ----
    int g = lane >> 2, t = lane & 3;
    #pragma unroll
    for (int nt = 0; nt < 8; nt++) {
        int nc = n0 + wn * 64 + nt * 8 + t * 2;
        int h_ = nc >> 6, d = nc & 63;
        float b0 = bias[nc], b1 = bias[nc + 1];
        #pragma unroll
        for (int mt = 0; mt < 2; mt++) {
            #pragma unroll
            for (int half = 0; half < 2; half++) {
                int m = m0 + wm * 32 + mt * 16 + g + half * 8;
                int b_ = m >> 10, s_ = m & 1023;
                float2 o;
                o.x = acc[mt][nt][half * 2 + 0] + b0;
                o.y = acc[mt][nt][half * 2 + 1] + b1;
                *(float2*)&outm[((size_t)(b_ * HH + h_) * SS + s_) * DD + d] = o;
            }
        }
    }
}

// ---------------------------------------------------------------------------
// Attention (unchanged): one CTA = 64 query rows of one (b,h).
// ---------------------------------------------------------------------------
#define PADQ 68
#define PADE 129
#define PADP 65

#define SM_QT   0
#define SM_KT   (SM_QT + 64 * PADQ)
#define SM_VS   (SM_KT + 64 * PADQ)
#define SM_ET   (SM_VS + 64 * 64)
#define SM_PS   (SM_ET + 64 * PADE)
#define SM_RED  (SM_PS + 64 * PADP)
#define SM_AM   (SM_RED + 64 * 16)
#define SM_SK   (SM_AM + 64)
#define SM_FLOATS (SM_SK + 64)
#define SM_BYTES (SM_FLOATS * 4)

__global__ __launch_bounds__(256) void attn_kernel(
    const float* __restrict__ amask,   // [B,1,1,S]
    const int*   __restrict__ skim,    // [B,S]
    const float* __restrict__ E,       // [2047, 64]
    float* __restrict__ out)           // [B,S,H,D]
{
    extern __shared__ float sm[];
    float* Qt  = sm + SM_QT;
    float* Kt  = sm + SM_KT;
    float* Vs  = sm + SM_VS;
    float* Et  = sm + SM_ET;
    float* Ps  = sm + SM_PS;
    float* red = sm + SM_RED;
    float* ams = sm + SM_AM;
    float* sks = sm + SM_SK;

    int tid = threadIdx.x;
    int ty = tid >> 4, tx = tid & 15;
    int b = blockIdx.z, h = blockIdx.y;
    int l0 = blockIdx.x * 64;
    int bh = b * HH + h;
    const float* qp = g_q + (size_t)bh * SS * DD;
    const float* kp = g_k + (size_t)bh * SS * DD;
    const float* vp = g_v + (size_t)bh * SS * DD;

    #pragma unroll
    for (int p = 0; p < 16; p++) {
        int idx = tid + p * 256;
        int l = idx >> 6, d = idx & 63;
        Qt[d * PADQ + l] = qp[(l0 + l) * DD + d];
    }

    float acc[4][4] = {};
    float rsum[4] = {};
    int jjb = (ty - tx) * 4 + 63;

    for (int rt = 0; rt < 16; rt++) {
        int r0 = rt * 64;
        __syncthreads();

        #pragma unroll
        for (int p = 0; p < 16; p++) {
            int idx = tid + p * 256;
            int r = idx >> 6, d = idx & 63;
            Kt[d * PADQ + r] = kp[(r0 + r) * DD + d];
            Vs[r * 64 + d]   = vp[(r0 + r) * DD + d];
        }
        int jmin = l0 - r0 + 960;
        #pragma unroll
        for (int p = 0; p < 32; p++) {
            int idx = tid + p * 256;
            int jj = idx >> 6, d = idx & 63;
            Et[d * PADE + jj] = (jj < 127) ? E[(jmin + jj) * DD + d] : 0.0f;
        }
        if (tid < 64) {
            ams[tid] = amask[b * SS + r0 + tid];
            sks[tid] = (float)skim[b * SS + r0 + tid];
        }
        __syncthreads();

        float s[4][4] = {};
        #pragma unroll 4
        for (int d = 0; d < 64; d++) {
            float4 q4 = *(const float4*)&Qt[d * PADQ + ty * 4];
            float4 k4 = *(const float4*)&Kt[d * PADQ + tx * 4];
            float e[7];
            #pragma unroll
            for (int c = 0; c < 7; c++) e[c] = Et[d * PADE + jjb + c - 3];
            float q[4] = {q4.x, q4.y, q4.z, q4.w};
            float k[4] = {k4.x, k4.y, k4.z, k4.w};
            #pragma unroll
            for (int i = 0; i < 4; i++)
                #pragma unroll
                for (int j = 0; j < 4; j++)
                    s[i][j] += q[i] * (k[j] + e[i - j + 3]);
        }

        #pragma unroll
        for (int j = 0; j < 4; j++) {
            int rl = tx * 4 + j;
            float am = ams[rl];
            float sk = sks[rl];
            #pragma unroll
            for (int i = 0; i < 4; i++) {
                float p = __expf(s[i][j] * 0.125f + am) * sk;
                rsum[i] += p;
                Ps[(ty * 4 + i) * PADP + rl] = p;
            }
        }
        __syncthreads();

        #pragma unroll 8
        for (int r = 0; r < 64; r++) {
            float4 v4 = *(const float4*)&Vs[r * 64 + tx * 4];
            float v[4] = {v4.x, v4.y, v4.z, v4.w};
            #pragma unroll
            for (int i = 0; i < 4; i++) {
                float p = Ps[(ty * 4 + i) * PADP + r];
                acc[i][0] += p * v[0];
                acc[i][1] += p * v[1];
                acc[i][2] += p * v[2];
                acc[i][3] += p * v[3];
            }
        }
    }

    __syncthreads();
    #pragma unroll
    for (int i = 0; i < 4; i++) red[(ty * 4 + i) * 16 + tx] = rsum[i];
    __syncthreads();

    #pragma unroll
    for (int i = 0; i < 4; i++) {
        float tot = 0.f;
        #pragma unroll
        for (int t = 0; t < 16; t++) tot += red[(ty * 4 + i) * 16 + t];
        float inv = 1.0f / (1e-8f + tot);
        int lg = l0 + ty * 4 + i;
        float4 o;
        o.x = acc[i][0] * inv;
        o.y = acc[i][1] * inv;
        o.z = acc[i][2] * inv;
        o.w = acc[i][3] * inv;
        *(float4*)&out[(((size_t)b * SS + lg) * HH + h) * DD + tx * 4] = o;
    }
}

extern "C" void kernel_launch(void* const* d_in, const int* in_sizes, int n_in,
                              void* d_out, int out_size)
{
    const float* hs    = (const float*)d_in[0];
    const float* amask = (const float*)d_in[1];
    const int*   skm   = (const int*)  d_in[2];
    const float* Wq    = (const float*)d_in[3];
    const float* bq    = (const float*)d_in[4];
    const float* Wk    = (const float*)d_in[5];
    const float* bk    = (const float*)d_in[6];
    const float* Wv    = (const float*)d_in[7];
    const float* bv    = (const float*)d_in[8];
    const float* E     = (const float*)d_in[9];
    float* out = (float*)d_out;

    cudaFuncSetAttribute(attn_kernel, cudaFuncAttributeMaxDynamicSharedMemorySize, SM_BYTES);

    qkv_tc_kernel<<<dim3(32, 24), 256>>>(hs, Wq, bq, Wk, bk, Wv, bv);
    attn_kernel<<<dim3(16, 16, 4), 256, SM_BYTES>>>(amask, skm, E, out);
}

// round 5
// speedup vs baseline: 2.1040x; 2.1040x over previous
#include <cuda_runtime.h>
#include <cuda_bf16.h>
#include <cstdint>
#include <cstddef>

#define BB 4
#define SS 1024
#define HIDD 1024
#define HH 16
#define DD 64

// scratch: q,k,v in [B,H,S,D] layout
__device__ float g_q[BB*HH*SS*DD];
__device__ float g_k[BB*HH*SS*DD];
__device__ float g_v[BB*HH*SS*DD];

// pre-converted bf16 split-precision operands
__device__ __nv_bfloat16 gAh[4096 * 1024];
__device__ __nv_bfloat16 gAl[4096 * 1024];
__device__ __nv_bfloat16 gBh[3 * 1024 * 1024];   // [sel][n][k] (transposed)
__device__ __nv_bfloat16 gBl[3 * 1024 * 1024];

__device__ __forceinline__ uint32_t smem_u32(const void* p) {
    uint32_t a;
    asm("{ .reg .u64 t; cvta.to.shared.u64 t, %1; cvt.u32.u64 %0, t; }" : "=r"(a) : "l"(p));
    return a;
}
__device__ __forceinline__ void ldsm_x4(uint32_t* r, uint32_t addr) {
    asm volatile("ldmatrix.sync.aligned.m8n8.x4.shared.b16 {%0,%1,%2,%3}, [%4];"
        : "=r"(r[0]), "=r"(r[1]), "=r"(r[2]), "=r"(r[3]) : "r"(addr));
}
__device__ __forceinline__ void mma16816(float* c, const uint32_t* a, const uint32_t* b) {
    asm volatile(
        "mma.sync.aligned.m16n8k16.row.col.f32.bf16.bf16.f32 "
        "{%0,%1,%2,%3}, {%4,%5,%6,%7}, {%8,%9}, {%0,%1,%2,%3};"
        : "+f"(c[0]), "+f"(c[1]), "+f"(c[2]), "+f"(c[3])
        : "r"(a[0]), "r"(a[1]), "r"(a[2]), "r"(a[3]), "r"(b[0]), "r"(b[1]));
}
__device__ __forceinline__ void cp16(uint32_t dst, const void* src) {
    asm volatile("cp.async.cg.shared.global [%0], [%1], 16;" :: "r"(dst), "l"(src));
}
#define CP_COMMIT() asm volatile("cp.async.commit_group;" ::: "memory")
#define CP_WAIT(N)  asm volatile("cp.async.wait_group %0;" :: "n"(N) : "memory")

__device__ __forceinline__ void split_bf16(float v, __nv_bfloat16& h, __nv_bfloat16& l) {
    h = __float2bfloat16_rn(v);
    l = __float2bfloat16_rn(v - __bfloat162float(h));
}

// ---------------------------------------------------------------------------
// conv_A: A fp32 [4096,1024] -> gAh/gAl bf16 (same layout). grid 4096 x 256.
// ---------------------------------------------------------------------------
__global__ __launch_bounds__(256) void conv_a_kernel(const float* __restrict__ A)
{
    int idx = blockIdx.x * 256 + threadIdx.x;   // float4 index
    float4 a4 = *(const float4*)&A[(size_t)idx * 4];
    __nv_bfloat16 h[4], l[4];
    split_bf16(a4.x, h[0], l[0]);
    split_bf16(a4.y, h[1], l[1]);
    split_bf16(a4.z, h[2], l[2]);
    split_bf16(a4.w, h[3], l[3]);
    *(uint2*)&gAh[(size_t)idx * 4] = *(uint2*)h;
    *(uint2*)&gAl[(size_t)idx * 4] = *(uint2*)l;
}

// ---------------------------------------------------------------------------
// conv_W: W fp32 [k][n] -> gB [sel][n][k] bf16 hi/lo (transpose).
// grid (32, 32, 3), block (32, 8).
// ---------------------------------------------------------------------------
__global__ __launch_bounds__(256) void conv_w_kernel(
    const float* __restrict__ Wq, const float* __restrict__ Wk, const float* __restrict__ Wv)
{
    __shared__ float t[32][33];
    int sel = blockIdx.z;
    const float* W = (sel == 0) ? Wq : (sel == 1) ? Wk : Wv;
    int n0 = blockIdx.x * 32, k0 = blockIdx.y * 32;
    int tx = threadIdx.x, ty = threadIdx.y;

    #pragma unroll
    for (int r = ty; r < 32; r += 8)
        t[r][tx] = W[(size_t)(k0 + r) * HIDD + n0 + tx];
    __syncthreads();
    size_t base = (size_t)sel * 1024 * 1024;
    #pragma unroll
    for (int r = ty; r < 32; r += 8) {
        float v = t[tx][r];
        __nv_bfloat16 h, l;
        split_bf16(v, h, l);
        gBh[base + (size_t)(n0 + r) * 1024 + k0 + tx] = h;
        gBl[base + (size_t)(n0 + r) * 1024 + k0 + tx] = l;
    }
}

// ---------------------------------------------------------------------------
// QKV GEMM: bf16 split-precision mma.sync, double-buffered cp.async.
// CTA tile 128x128, BK=32. 8 warps 4(m) x 2(n), each 32x64.
// grid (32, 24): x = m-tile, y = n-tile over [q|k|v].
// ---------------------------------------------------------------------------
#define APITCH 40            // bf16 elems/row in smem (80B, ldmatrix conflict-free)
#define TILE_B (128 * APITCH * 2)   // 10240 bytes per tile
#define STAGE_B (4 * TILE_B)        // Ah, Al, Bh, Bl
#define QSM_BYTES (2 * STAGE_B)     // double buffer: 81920

__global__ __launch_bounds__(256, 2) void qkv_tc_kernel(
    const float* __restrict__ bq, const float* __restrict__ bk, const float* __restrict__ bv)
{
    extern __shared__ char smc[];
    uint32_t sb = smem_u32(smc);

    int tid  = threadIdx.x;
    int wid  = tid >> 5;
    int lane = tid & 31;
    int wm = wid & 3;
    int wn = wid >> 2;

    int m0  = blockIdx.x * 128;
    int ng0 = blockIdx.y * 128;
    int sel = ng0 >> 10;
    int n0  = ng0 & 1023;

    const float* bias = (sel == 0) ? bq : (sel == 1) ? bk : bv;
    float* outm       = (sel == 0) ? g_q : (sel == 1) ? g_k : g_v;

    const __nv_bfloat16* pAh = gAh + (size_t)m0 * 1024;
    const __nv_bfloat16* pAl = gAl + (size_t)m0 * 1024;
    const __nv_bfloat16* pBh = gBh + (size_t)sel * 1048576 + (size_t)n0 * 1024;
    const __nv_bfloat16* pBl = gBl + (size_t)sel * 1048576 + (size_t)n0 * 1024;

    // copy one stage (k0 = s*32) into buffer buf
    auto copy_stage = [&](int s, int buf) {
        int k0 = s * 32;
        uint32_t bbase = sb + buf * STAGE_B;
        #pragma unroll
        for (int p = 0; p < 8; p++) {
            int tile = p >> 1;                    // 0=Ah 1=Al 2=Bh 3=Bl
            int cidx = tid + (p & 1) * 256;       // 0..511
            int row = cidx >> 2, ch = cidx & 3;
            const __nv_bfloat16* src =
                (tile == 0) ? pAh : (tile == 1) ? pAl : (tile == 2) ? pBh : pBl;
            cp16(bbase + tile * TILE_B + row * (APITCH * 2) + ch * 16,
                 src + (size_t)row * 1024 + k0 + ch * 8);
        }
        CP_COMMIT();
    };

    float acc[2][8][4] = {};

    int a_row = (lane & 15);
    int a_kof = (lane >> 4) * 8;
    int b_nof = (lane & 7) | ((lane >> 4) << 3);
    int b_kof = ((lane >> 3) & 1) * 8;

    copy_stage(0, 0);

    for (int s = 0; s < 32; s++) {
        int buf = s & 1;
        if (s + 1 < 32) {
            copy_stage(s + 1, buf ^ 1);
            CP_WAIT(1);
        } else {
            CP_WAIT(0);
        }
        __syncthreads();

        uint32_t bAh = sb + buf * STAGE_B;
        uint32_t bAl = bAh + TILE_B;
        uint32_t bBh = bAl + TILE_B;
        uint32_t bBl = bBh + TILE_B;

        #pragma unroll
        for (int kk = 0; kk < 32; kk += 16) {
            uint32_t ah[2][4], al[2][4];
            #pragma unroll
            for (int mt = 0; mt < 2; mt++) {
                int off = ((wm * 32 + mt * 16 + a_row) * APITCH + kk + a_kof) * 2;
                ldsm_x4(ah[mt], bAh + off);
                ldsm_x4(al[mt], bAl + off);
            }
            #pragma unroll
            for (int np = 0; np < 4; np++) {
                uint32_t bh4[4], bl4[4];
                int off = ((wn * 64 + np * 16 + b_nof) * APITCH + kk + b_kof) * 2;
                ldsm_x4(bh4, bBh + off);
                ldsm_x4(bl4, bBl + off);
                #pragma unroll
                for (int mt = 0; mt < 2; mt++)
                    #pragma unroll
                    for (int t = 0; t < 2; t++) {
                        float* c = acc[mt][np * 2 + t];
                        mma16816(c, ah[mt], &bh4[t * 2]);
                        mma16816(c, ah[mt], &bl4[t * 2]);
                        mma16816(c, al[mt], &bh4[t * 2]);
                    }
            }
        }
        __syncthreads();
    }

    // epilogue: bias + store to [B,H,S,D]
    int g = lane >> 2, t = lane & 3;
    #pragma unroll
    for (int nt = 0; nt < 8; nt++) {
        int nc = n0 + wn * 64 + nt * 8 + t * 2;
        int h_ = nc >> 6, d = nc & 63;
        float b0 = bias[nc], b1 = bias[nc + 1];
        #pragma unroll
        for (int mt = 0; mt < 2; mt++) {
            #pragma unroll
            for (int half = 0; half < 2; half++) {
                int m = m0 + wm * 32 + mt * 16 + g + half * 8;
                int b_ = m >> 10, s_ = m & 1023;
                float2 o;
                o.x = acc[mt][nt][half * 2 + 0] + b0;
                o.y = acc[mt][nt][half * 2 + 1] + b1;
                *(float2*)&outm[((size_t)(b_ * HH + h_) * SS + s_) * DD + d] = o;
            }
        }
    }
}

// ---------------------------------------------------------------------------
// Attention (unchanged): one CTA = 64 query rows of one (b,h).
// ---------------------------------------------------------------------------
#define PADQ 68
#define PADE 129
#define PADP 65

#define SM_QT   0
#define SM_KT   (SM_QT + 64 * PADQ)
#define SM_VS   (SM_KT + 64 * PADQ)
#define SM_ET   (SM_VS + 64 * 64)
#define SM_PS   (SM_ET + 64 * PADE)
#define SM_RED  (SM_PS + 64 * PADP)
#define SM_AM   (SM_RED + 64 * 16)
#define SM_SK   (SM_AM + 64)
#define SM_FLOATS (SM_SK + 64)
#define SM_BYTES (SM_FLOATS * 4)

__global__ __launch_bounds__(256) void attn_kernel(
    const float* __restrict__ amask,   // [B,1,1,S]
    const int*   __restrict__ skim,    // [B,S]
    const float* __restrict__ E,       // [2047, 64]
    float* __restrict__ out)           // [B,S,H,D]
{
    extern __shared__ float sm[];
    float* Qt  = sm + SM_QT;
    float* Kt  = sm + SM_KT;
    float* Vs  = sm + SM_VS;
    float* Et  = sm + SM_ET;
    float* Ps  = sm + SM_PS;
    float* red = sm + SM_RED;
    float* ams = sm + SM_AM;
    float* sks = sm + SM_SK;

    int tid = threadIdx.x;
    int ty = tid >> 4, tx = tid & 15;
    int b = blockIdx.z, h = blockIdx.y;
    int l0 = blockIdx.x * 64;
    int bh = b * HH + h;
    const float* qp = g_q + (size_t)bh * SS * DD;
    const float* kp = g_k + (size_t)bh * SS * DD;
    const float* vp = g_v + (size_t)bh * SS * DD;

    #pragma unroll
    for (int p = 0; p < 16; p++) {
        int idx = tid + p * 256;
        int l = idx >> 6, d = idx & 63;
        Qt[d * PADQ + l] = qp[(l0 + l) * DD + d];
    }

    float acc[4][4] = {};
    float rsum[4] = {};
    int jjb = (ty - tx) * 4 + 63;

    for (int rt = 0; rt < 16; rt++) {
        int r0 = rt * 64;
        __syncthreads();

        #pragma unroll
        for (int p = 0; p < 16; p++) {
            int idx = tid + p * 256;
            int r = idx >> 6, d = idx & 63;
            Kt[d * PADQ + r] = kp[(r0 + r) * DD + d];
            Vs[r * 64 + d]   = vp[(r0 + r) * DD + d];
        }
        int jmin = l0 - r0 + 960;
        #pragma unroll
        for (int p = 0; p < 32; p++) {
            int idx = tid + p * 256;
            int jj = idx >> 6, d = idx & 63;
            Et[d * PADE + jj] = (jj < 127) ? E[(jmin + jj) * DD + d] : 0.0f;
        }
        if (tid < 64) {
            ams[tid] = amask[b * SS + r0 + tid];
            sks[tid] = (float)skim[b * SS + r0 + tid];
        }
        __syncthreads();

        float s[4][4] = {};
        #pragma unroll 4
        for (int d = 0; d < 64; d++) {
            float4 q4 = *(const float4*)&Qt[d * PADQ + ty * 4];
            float4 k4 = *(const float4*)&Kt[d * PADQ + tx * 4];
            float e[7];
            #pragma unroll
            for (int c = 0; c < 7; c++) e[c] = Et[d * PADE + jjb + c - 3];
            float q[4] = {q4.x, q4.y, q4.z, q4.w};
            float k[4] = {k4.x, k4.y, k4.z, k4.w};
            #pragma unroll
            for (int i = 0; i < 4; i++)
                #pragma unroll
                for (int j = 0; j < 4; j++)
                    s[i][j] += q[i] * (k[j] + e[i - j + 3]);
        }

        #pragma unroll
        for (int j = 0; j < 4; j++) {
            int rl = tx * 4 + j;
            float am = ams[rl];
            float sk = sks[rl];
            #pragma unroll
            for (int i = 0; i < 4; i++) {
                float p = __expf(s[i][j] * 0.125f + am) * sk;
                rsum[i] += p;
                Ps[(ty * 4 + i) * PADP + rl] = p;
            }
        }
        __syncthreads();

        #pragma unroll 8
        for (int r = 0; r < 64; r++) {
            float4 v4 = *(const float4*)&Vs[r * 64 + tx * 4];
            float v[4] = {v4.x, v4.y, v4.z, v4.w};
            #pragma unroll
            for (int i = 0; i < 4; i++) {
                float p = Ps[(ty * 4 + i) * PADP + r];
                acc[i][0] += p * v[0];
                acc[i][1] += p * v[1];
                acc[i][2] += p * v[2];
                acc[i][3] += p * v[3];
            }
        }
    }

    __syncthreads();
    #pragma unroll
    for (int i = 0; i < 4; i++) red[(ty * 4 + i) * 16 + tx] = rsum[i];
    __syncthreads();

    #pragma unroll
    for (int i = 0; i < 4; i++) {
        float tot = 0.f;
        #pragma unroll
        for (int t = 0; t < 16; t++) tot += red[(ty * 4 + i) * 16 + t];
        float inv = 1.0f / (1e-8f + tot);
        int lg = l0 + ty * 4 + i;
        float4 o;
        o.x = acc[i][0] * inv;
        o.y = acc[i][1] * inv;
        o.z = acc[i][2] * inv;
        o.w = acc[i][3] * inv;
        *(float4*)&out[(((size_t)b * SS + lg) * HH + h) * DD + tx * 4] = o;
    }
}

extern "C" void kernel_launch(void* const* d_in, const int* in_sizes, int n_in,
                              void* d_out, int out_size)
{
    const float* hs    = (const float*)d_in[0];
    const float* amask = (const float*)d_in[1];
    const int*   skm   = (const int*)  d_in[2];
    const float* Wq    = (const float*)d_in[3];
    const float* bq    = (const float*)d_in[4];
    const float* Wk    = (const float*)d_in[5];
    const float* bk    = (const float*)d_in[6];
    const float* Wv    = (const float*)d_in[7];
    const float* bv    = (const float*)d_in[8];
    const float* E     = (const float*)d_in[9];
    float* out = (float*)d_out;

    cudaFuncSetAttribute(qkv_tc_kernel, cudaFuncAttributeMaxDynamicSharedMemorySize, QSM_BYTES);
    cudaFuncSetAttribute(attn_kernel, cudaFuncAttributeMaxDynamicSharedMemorySize, SM_BYTES);

    conv_a_kernel<<<4096, 256>>>(hs);
    conv_w_kernel<<<dim3(32, 32, 3), dim3(32, 8)>>>(Wq, Wk, Wv);
    qkv_tc_kernel<<<dim3(32, 24), 256, QSM_BYTES>>>(bq, bk, bv);
    attn_kernel<<<dim3(16, 16, 4), 256, SM_BYTES>>>(amask, skm, E, out);
}

// round 6
// speedup vs baseline: 2.4753x; 1.1765x over previous
#include <cuda_runtime.h>
#include <cuda_bf16.h>
#include <cstdint>
#include <cstddef>

#define BB 4
#define SS 1024
#define HIDD 1024
#define HH 16
#define DD 64

// scratch: q,k,v in [B,H,S,D] layout (fp32, from qkv)
__device__ float g_q[BB*HH*SS*DD];
__device__ float g_k[BB*HH*SS*DD];
__device__ float g_v[BB*HH*SS*DD];

// pre-converted bf16 split operands for qkv GEMM
__device__ __nv_bfloat16 gAh[4096 * 1024];
__device__ __nv_bfloat16 gAl[4096 * 1024];
__device__ __nv_bfloat16 gBh[3 * 1024 * 1024];   // [sel][n][k]
__device__ __nv_bfloat16 gBl[3 * 1024 * 1024];

// bf16 split q/k/v for attention
__device__ __nv_bfloat16 gQh[BB*HH*SS*DD];
__device__ __nv_bfloat16 gQl[BB*HH*SS*DD];
__device__ __nv_bfloat16 gKh[BB*HH*SS*DD];
__device__ __nv_bfloat16 gKl[BB*HH*SS*DD];
__device__ __nv_bfloat16 gVth[BB*HH*DD*SS];      // [bh][d][s] transposed
__device__ __nv_bfloat16 gVtl[BB*HH*DD*SS];
__device__ __nv_bfloat16 gEh[2047 * 64];         // dist_emb bf16 (hi)
__device__ float gWcomb[BB * SS];                // exp(amask)*skim

__device__ __forceinline__ uint32_t smem_u32(const void* p) {
    uint32_t a;
    asm("{ .reg .u64 t; cvta.to.shared.u64 t, %1; cvt.u32.u64 %0, t; }" : "=r"(a) : "l"(p));
    return a;
}
__device__ __forceinline__ void ldsm_x4(uint32_t* r, uint32_t addr) {
    asm volatile("ldmatrix.sync.aligned.m8n8.x4.shared.b16 {%0,%1,%2,%3}, [%4];"
        : "=r"(r[0]), "=r"(r[1]), "=r"(r[2]), "=r"(r[3]) : "r"(addr));
}
__device__ __forceinline__ void mma16816(float* c, const uint32_t* a, const uint32_t* b) {
    asm volatile(
        "mma.sync.aligned.m16n8k16.row.col.f32.bf16.bf16.f32 "
        "{%0,%1,%2,%3}, {%4,%5,%6,%7}, {%8,%9}, {%0,%1,%2,%3};"
        : "+f"(c[0]), "+f"(c[1]), "+f"(c[2]), "+f"(c[3])
        : "r"(a[0]), "r"(a[1]), "r"(a[2]), "r"(a[3]), "r"(b[0]), "r"(b[1]));
}
__device__ __forceinline__ void cp16(uint32_t dst, const void* src) {
    asm volatile("cp.async.cg.shared.global [%0], [%1], 16;" :: "r"(dst), "l"(src));
}
#define CP_COMMIT() asm volatile("cp.async.commit_group;" ::: "memory")
#define CP_WAIT(N)  asm volatile("cp.async.wait_group %0;" :: "n"(N) : "memory")

__device__ __forceinline__ void split_bf16(float v, __nv_bfloat16& h, __nv_bfloat16& l) {
    h = __float2bfloat16_rn(v);
    l = __float2bfloat16_rn(v - __bfloat162float(h));
}

// ---------------------------------------------------------------------------
// conv_A: hidden fp32 -> gAh/gAl
// ---------------------------------------------------------------------------
__global__ __launch_bounds__(256) void conv_a_kernel(const float* __restrict__ A)
{
    int idx = blockIdx.x * 256 + threadIdx.x;
    float4 a4 = *(const float4*)&A[(size_t)idx * 4];
    __nv_bfloat16 h[4], l[4];
    split_bf16(a4.x, h[0], l[0]);
    split_bf16(a4.y, h[1], l[1]);
    split_bf16(a4.z, h[2], l[2]);
    split_bf16(a4.w, h[3], l[3]);
    *(uint2*)&gAh[(size_t)idx * 4] = *(uint2*)h;
    *(uint2*)&gAl[(size_t)idx * 4] = *(uint2*)l;
}

// ---------------------------------------------------------------------------
// conv_W: W fp32 [k][n] -> gB [sel][n][k] bf16 hi/lo (transpose).
// ---------------------------------------------------------------------------
__global__ __launch_bounds__(256) void conv_w_kernel(
    const float* __restrict__ Wq, const float* __restrict__ Wk, const float* __restrict__ Wv)
{
    __shared__ float t[32][33];
    int sel = blockIdx.z;
    const float* W = (sel == 0) ? Wq : (sel == 1) ? Wk : Wv;
    int n0 = blockIdx.x * 32, k0 = blockIdx.y * 32;
    int tx = threadIdx.x, ty = threadIdx.y;

    #pragma unroll
    for (int r = ty; r < 32; r += 8)
        t[r][tx] = W[(size_t)(k0 + r) * HIDD + n0 + tx];
    __syncthreads();
    size_t base = (size_t)sel * 1024 * 1024;
    #pragma unroll
    for (int r = ty; r < 32; r += 8) {
        float v = t[tx][r];
        __nv_bfloat16 h, l;
        split_bf16(v, h, l);
        gBh[base + (size_t)(n0 + r) * 1024 + k0 + tx] = h;
        gBl[base + (size_t)(n0 + r) * 1024 + k0 + tx] = l;
    }
}

// ---------------------------------------------------------------------------
// conv_E: dist_emb fp32 -> bf16 hi
// ---------------------------------------------------------------------------
__global__ __launch_bounds__(256) void conv_e_kernel(const float* __restrict__ E)
{
    int i4 = blockIdx.x * 256 + threadIdx.x;
    if (i4 < 2047 * 16) {
        float4 a4 = *(const float4*)&E[(size_t)i4 * 4];
        __nv_bfloat16 h[4];
        h[0] = __float2bfloat16_rn(a4.x);
        h[1] = __float2bfloat16_rn(a4.y);
        h[2] = __float2bfloat16_rn(a4.z);
        h[3] = __float2bfloat16_rn(a4.w);
        *(uint2*)&gEh[(size_t)i4 * 4] = *(uint2*)h;
    }
}

// ---------------------------------------------------------------------------
// conv_mask: w[b][r] = exp(amask[b,r]) * skim[b,r]
// ---------------------------------------------------------------------------
__global__ __launch_bounds__(256) void conv_mask_kernel(
    const float* __restrict__ am, const int* __restrict__ sk)
{
    int i = blockIdx.x * 256 + threadIdx.x;
    gWcomb[i] = __expf(am[i]) * (float)sk[i];
}

// ---------------------------------------------------------------------------
// QKV GEMM (unchanged from round 5, proven): writes fp32 g_q/g_k/g_v
// ---------------------------------------------------------------------------
#define APITCH 40
#define TILE_B (128 * APITCH * 2)
#define STAGE_B (4 * TILE_B)
#define QSM_BYTES (2 * STAGE_B)

__global__ __launch_bounds__(256, 2) void qkv_tc_kernel(
    const float* __restrict__ bq, const float* __restrict__ bk, const float* __restrict__ bv)
{
    extern __shared__ char smc[];
    uint32_t sb = smem_u32(smc);

    int tid  = threadIdx.x;
    int wid  = tid >> 5;
    int lane = tid & 31;
    int wm = wid & 3;
    int wn = wid >> 2;

    int m0  = blockIdx.x * 128;
    int ng0 = blockIdx.y * 128;
    int sel = ng0 >> 10;
    int n0  = ng0 & 1023;

    const float* bias = (sel == 0) ? bq : (sel == 1) ? bk : bv;
    float* outm       = (sel == 0) ? g_q : (sel == 1) ? g_k : g_v;

    const __nv_bfloat16* pAh = gAh + (size_t)m0 * 1024;
    const __nv_bfloat16* pAl = gAl + (size_t)m0 * 1024;
    const __nv_bfloat16* pBh = gBh + (size_t)sel * 1048576 + (size_t)n0 * 1024;
    const __nv_bfloat16* pBl = gBl + (size_t)sel * 1048576 + (size_t)n0 * 1024;

    auto copy_stage = [&](int s, int buf) {
        int k0 = s * 32;
        uint32_t bbase = sb + buf * STAGE_B;
        #pragma unroll
        for (int p = 0; p < 8; p++) {
            int tile = p >> 1;
            int cidx = tid + (p & 1) * 256;
            int row = cidx >> 2, ch = cidx & 3;
            const __nv_bfloat16* src =
                (tile == 0) ? pAh : (tile == 1) ? pAl : (tile == 2) ? pBh : pBl;
            cp16(bbase + tile * TILE_B + row * (APITCH * 2) + ch * 16,
                 src + (size_t)row * 1024 + k0 + ch * 8);
        }
        CP_COMMIT();
    };

    float acc[2][8][4] = {};

    int a_row = (lane & 15);
    int a_kof = (lane >> 4) * 8;
    int b_nof = (lane & 7) | ((lane >> 4) << 3);
    int b_kof = ((lane >> 3) & 1) * 8;

    copy_stage(0, 0);

    for (int s = 0; s < 32; s++) {
        int buf = s & 1;
        if (s + 1 < 32) {
            copy_stage(s + 1, buf ^ 1);
            CP_WAIT(1);
        } else {
            CP_WAIT(0);
        }
        __syncthreads();

        uint32_t bAh = sb + buf * STAGE_B;
        uint32_t bAl = bAh + TILE_B;
        uint32_t bBh = bAl + TILE_B;
        uint32_t bBl = bBh + TILE_B;

        #pragma unroll
        for (int kk = 0; kk < 32; kk += 16) {
            uint32_t ah[2][4], al[2][4];
            #pragma unroll
            for (int mt = 0; mt < 2; mt++) {
                int off = ((wm * 32 + mt * 16 + a_row) * APITCH + kk + a_kof) * 2;
                ldsm_x4(ah[mt], bAh + off);
                ldsm_x4(al[mt], bAl + off);
            }
            #pragma unroll
            for (int np = 0; np < 4; np++) {
                uint32_t bh4[4], bl4[4];
                int off = ((wn * 64 + np * 16 + b_nof) * APITCH + kk + b_kof) * 2;
                ldsm_x4(bh4, bBh + off);
                ldsm_x4(bl4, bBl + off);
                #pragma unroll
                for (int mt = 0; mt < 2; mt++)
                    #pragma unroll
                    for (int t = 0; t < 2; t++) {
                        float* c = acc[mt][np * 2 + t];
                        mma16816(c, ah[mt], &bh4[t * 2]);
                        mma16816(c, ah[mt], &bl4[t * 2]);
                        mma16816(c, al[mt], &bh4[t * 2]);
                    }
            }
        }
        __syncthreads();
    }

    int g = lane >> 2, t = lane & 3;
    #pragma unroll
    for (int nt = 0; nt < 8; nt++) {
        int nc = n0 + wn * 64 + nt * 8 + t * 2;
        int h_ = nc >> 6, d = nc & 63;
        float b0 = bias[nc], b1 = bias[nc + 1];
        #pragma unroll
        for (int mt = 0; mt < 2; mt++) {
            #pragma unroll
            for (int half = 0; half < 2; half++) {
                int m = m0 + wm * 32 + mt * 16 + g + half * 8;
                int b_ = m >> 10, s_ = m & 1023;
                float2 o;
                o.x = acc[mt][nt][half * 2 + 0] + b0;
                o.y = acc[mt][nt][half * 2 + 1] + b1;
                *(float2*)&outm[((size_t)(b_ * HH + h_) * SS + s_) * DD + d] = o;
            }
        }
    }
}

// ---------------------------------------------------------------------------
// conv_split: fp32 q/k/v -> bf16 split; v transposed to [bh][d][s].
// grid (64, 16) = (bh, s-tile of 64), block 256.
// ---------------------------------------------------------------------------
__global__ __launch_bounds__(256) void conv_split_kernel()
{
    __shared__ float vt[64][65];
    int bh = blockIdx.x;
    int s0 = blockIdx.y * 64;
    int tid = threadIdx.x;
    size_t base = (size_t)bh * SS * DD + (size_t)s0 * DD;
    const float* q = g_q + base;
    const float* k = g_k + base;
    const float* v = g_v + base;

    #pragma unroll
    for (int p = 0; p < 4; p++) {
        int i4 = tid + p * 256;                 // (s, d4)
        int s_ = i4 >> 4, d4 = (i4 & 15) * 4;
        size_t go = base + (size_t)s_ * 64 + d4;

        float4 a = *(const float4*)&q[(size_t)s_ * 64 + d4];
        __nv_bfloat16 h[4], l[4];
        split_bf16(a.x, h[0], l[0]); split_bf16(a.y, h[1], l[1]);
        split_bf16(a.z, h[2], l[2]); split_bf16(a.w, h[3], l[3]);
        *(uint2*)&gQh[go] = *(uint2*)h;
        *(uint2*)&gQl[go] = *(uint2*)l;

        a = *(const float4*)&k[(size_t)s_ * 64 + d4];
        split_bf16(a.x, h[0], l[0]); split_bf16(a.y, h[1], l[1]);
        split_bf16(a.z, h[2], l[2]); split_bf16(a.w, h[3], l[3]);
        *(uint2*)&gKh[go] = *(uint2*)h;
        *(uint2*)&gKl[go] = *(uint2*)l;

        a = *(const float4*)&v[(size_t)s_ * 64 + d4];
        vt[d4 + 0][s_] = a.x;
        vt[d4 + 1][s_] = a.y;
        vt[d4 + 2][s_] = a.z;
        vt[d4 + 3][s_] = a.w;
    }
    __syncthreads();
    #pragma unroll
    for (int p = 0; p < 4; p++) {
        int i4 = tid + p * 256;
        int d = i4 >> 4, s4 = (i4 & 15) * 4;
        __nv_bfloat16 h[4], l[4];
        split_bf16(vt[d][s4 + 0], h[0], l[0]);
        split_bf16(vt[d][s4 + 1], h[1], l[1]);
        split_bf16(vt[d][s4 + 2], h[2], l[2]);
        split_bf16(vt[d][s4 + 3], h[3], l[3]);
        size_t go = (size_t)bh * DD * SS + (size_t)d * SS + s0 + s4;
        *(uint2*)&gVth[go] = *(uint2*)h;
        *(uint2*)&gVtl[go] = *(uint2*)l;
    }
}

// ---------------------------------------------------------------------------
// attn_tc: tensor-core attention with relative-position bias GEMM + gather.
// CTA = 128 queries x one (b,h), 256 threads (8 warps, m16 each).
// Per 64-key tile: T = Qh @ E_band^T; S = QK^T (split); p = exp((S+T)/8)*w;
// O += P @ V (split). grid (8, 16, 4).
// ---------------------------------------------------------------------------
#define EPITCH 72      // bf16 elems per row (144 B; ldmatrix conflict-free)
#define ROWB 144
#define TPITCH 200
#define SQH 0
#define SQL 18432
#define SKV 36864      // 8 tiles of 9216: [KH0,KH1,KL0,KL1,VH0,VH1,VL0,VL1]
#define SE  110592     // 192 rows x 144 = 27648
#define ST  138240     // 128 x 200 x 2 = 51200
#define SPH 189440
#define SPL 207872
#define SW  226304     // 1024 floats
#define ASM_BYTES 230400

__global__ __launch_bounds__(256, 1) void attn_tc_kernel(float* __restrict__ out)
{
    extern __shared__ char smc[];
    uint32_t sb = smem_u32(smc);
    int tid = threadIdx.x, wm = tid >> 5, lane = tid & 31;
    int b = blockIdx.z, h = blockIdx.y;
    int l0 = blockIdx.x * 128;
    int bh = b * HH + h;

    const __nv_bfloat16* pQh = gQh + ((size_t)bh * SS + l0) * DD;
    const __nv_bfloat16* pQl = gQl + ((size_t)bh * SS + l0) * DD;
    const __nv_bfloat16* pKh = gKh + (size_t)bh * SS * DD;
    const __nv_bfloat16* pKl = gKl + (size_t)bh * SS * DD;
    const __nv_bfloat16* pVh = gVth + (size_t)bh * DD * SS;
    const __nv_bfloat16* pVl = gVtl + (size_t)bh * DD * SS;

    int a_row = lane & 15;
    int a_kof = (lane >> 4) * 8;
    int b_nof = (lane & 7) | ((lane >> 4) << 3);
    int b_kof = ((lane >> 3) & 1) * 8;
    int g = lane >> 2, t = lane & 3;

    auto load_kv = [&](int s2, int b2) {
        int rr = s2 * 64;
        #pragma unroll
        for (int p = 0; p < 8; p++) {
            int idx = tid + p * 256;
            int arr = idx >> 9, rc = idx & 511;
            int row = rc >> 3, ch = rc & 7;
            const __nv_bfloat16* src =
                (arr == 0) ? pKh + (size_t)(rr + row) * 64 + ch * 8 :
                (arr == 1) ? pKl + (size_t)(rr + row) * 64 + ch * 8 :
                (arr == 2) ? pVh + (size_t)row * SS + rr + ch * 8 :
                             pVl + (size_t)row * SS + rr + ch * 8;
            cp16(sb + SKV + (arr * 2 + b2) * 9216 + row * ROWB + ch * 16, src);
        }
    };
    auto load_e = [&](int s2) {
        int base = l0 - s2 * 64 + 960;
        #pragma unroll
        for (int p = 0; p < 6; p++) {
            int idx = tid + p * 256;
            if (idx < 1528) {
                int row = idx >> 3, ch = idx & 7;
                cp16(sb + SE + row * ROWB + ch * 16,
                     gEh + (size_t)(base + row) * 64 + ch * 8);
            }
        }
    };

    // prologue: Q hi/lo (2048 cps), w (256 cps), tile 0
    #pragma unroll
    for (int p = 0; p < 8; p++) {
        int idx = tid + p * 256;
        int arr = idx >> 10, rc = idx & 1023;
        int row = rc >> 3, ch = rc & 7;
        cp16(sb + (arr ? SQL : SQH) + row * ROWB + ch * 16,
             (arr ? pQl : pQh) + (size_t)row * 64 + ch * 8);
    }
    cp16(sb + SW + tid * 16, gWcomb + b * SS + tid * 4);
    load_kv(0, 0);
    load_e(0);
    CP_COMMIT();

    float oacc[8][4] = {};
    float rs0 = 0.f, rs1 = 0.f;

    for (int s = 0; s < 16; s++) {
        int buf = s & 1;
        int r0 = s * 64;
        CP_WAIT(0);
        __syncthreads();

        // ---- bias GEMM: T[128 x 191] = Qh @ E_band^T (hi only), 3 chunks ----
        #pragma unroll
        for (int c = 0; c < 3; c++) {
            float tac[8][4] = {};
            #pragma unroll
            for (int kk = 0; kk < 64; kk += 16) {
                uint32_t ah4[4];
                ldsm_x4(ah4, sb + SQH + ((wm * 16 + a_row) * EPITCH + kk + a_kof) * 2);
                #pragma unroll
                for (int np = 0; np < 4; np++) {
                    uint32_t eb4[4];
                    ldsm_x4(eb4, sb + SE + ((c * 64 + np * 16 + b_nof) * EPITCH + kk + b_kof) * 2);
                    mma16816(tac[np * 2 + 0], ah4, &eb4[0]);
                    mma16816(tac[np * 2 + 1], ah4, &eb4[2]);
                }
            }
            #pragma unroll
            for (int nt = 0; nt < 8; nt++) {
                int col = c * 64 + nt * 8 + t * 2;
                int i0 = wm * 16 + g;
                __nv_bfloat162 v0, v1;
                v0.x = __float2bfloat16_rn(tac[nt][0]);
                v0.y = __float2bfloat16_rn(tac[nt][1]);
                v1.x = __float2bfloat16_rn(tac[nt][2]);
                v1.y = __float2bfloat16_rn(tac[nt][3]);
                *(__nv_bfloat162*)(smc + ST + ((size_t)i0 * TPITCH + col) * 2) = v0;
                *(__nv_bfloat162*)(smc + ST + ((size_t)(i0 + 8) * TPITCH + col) * 2) = v1;
            }
        }
        __syncthreads();   // E consumed; T visible

        // ---- prefetch next tile (E buffer now free) ----
        if (s + 1 < 16) {
            load_kv(s + 1, buf ^ 1);
            load_e(s + 1);
        }
        CP_COMMIT();

        // ---- QK^T (split precision) ----
        float sac[8][4] = {};
        uint32_t khb = sb + SKV + (0 * 2 + buf) * 9216;
        uint32_t klb = sb + SKV + (1 * 2 + buf) * 9216;
        #pragma unroll
        for (int kk = 0; kk < 64; kk += 16) {
            uint32_t ah4[4], al4[4];
            ldsm_x4(ah4, sb + SQH + ((wm * 16 + a_row) * EPITCH + kk + a_kof) * 2);
            ldsm_x4(al4, sb + SQL + ((wm * 16 + a_row) * EPITCH + kk + a_kof) * 2);
            #pragma unroll
            for (int np = 0; np < 4; np++) {
                uint32_t bh4[4], bl4[4];
                ldsm_x4(bh4, khb + ((np * 16 + b_nof) * EPITCH + kk + b_kof) * 2);
                ldsm_x4(bl4, klb + ((np * 16 + b_nof) * EPITCH + kk + b_kof) * 2);
                #pragma unroll
                for (int t2 = 0; t2 < 2; t2++) {
                    float* cc = sac[np * 2 + t2];
                    mma16816(cc, ah4, &bh4[t2 * 2]);
                    mma16816(cc, ah4, &bl4[t2 * 2]);
                    mma16816(cc, al4, &bh4[t2 * 2]);
                }
            }
        }

        // ---- epilogue: gather T, exp, split P ----
        {
            int i0 = wm * 16 + g, i1 = i0 + 8;
            #pragma unroll
            for (int nt = 0; nt < 8; nt++) {
                int j = nt * 8 + t * 2;
                float w0 = *(const float*)(smc + SW + (r0 + j) * 4);
                float w1 = *(const float*)(smc + SW + (r0 + j + 1) * 4);
                int jj0 = i0 - j + 63;
                int jj2 = i1 - j + 63;
                float t00 = __bfloat162float(*(const __nv_bfloat16*)(smc + ST + ((size_t)i0 * TPITCH + jj0) * 2));
                float t01 = __bfloat162float(*(const __nv_bfloat16*)(smc + ST + ((size_t)i0 * TPITCH + jj0 - 1) * 2));
                float t10 = __bfloat162float(*(const __nv_bfloat16*)(smc + ST + ((size_t)i1 * TPITCH + jj2) * 2));
                float t11 = __bfloat162float(*(const __nv_bfloat16*)(smc + ST + ((size_t)i1 * TPITCH + jj2 - 1) * 2));
                float p0 = __expf((sac[nt][0] + t00) * 0.125f) * w0;
                float p1 = __expf((sac[nt][1] + t01) * 0.125f) * w1;
                float p2 = __expf((sac[nt][2] + t10) * 0.125f) * w0;
                float p3 = __expf((sac[nt][3] + t11) * 0.125f) * w1;
                rs0 += p0 + p1;
                rs1 += p2 + p3;
                __nv_bfloat162 ph0, pl0, ph1, pl1;
                split_bf16(p0, ph0.x, pl0.x);
                split_bf16(p1, ph0.y, pl0.y);
                split_bf16(p2, ph1.x, pl1.x);
                split_bf16(p3, ph1.y, pl1.y);
                *(__nv_bfloat162*)(smc + SPH + ((size_t)i0 * EPITCH + j) * 2) = ph0;
                *(__nv_bfloat162*)(smc + SPL + ((size_t)i0 * EPITCH + j) * 2) = pl0;
                *(__nv_bfloat162*)(smc + SPH + ((size_t)i1 * EPITCH + j) * 2) = ph1;
                *(__nv_bfloat162*)(smc + SPL + ((size_t)i1 * EPITCH + j) * 2) = pl1;
            }
        }
        __syncwarp();   // P is warp-local (same 16 rows)

        // ---- PV (split precision) ----
        uint32_t vhb = sb + SKV + (2 * 2 + buf) * 9216;
        uint32_t vlb = sb + SKV + (3 * 2 + buf) * 9216;
        #pragma unroll
        for (int kk = 0; kk < 64; kk += 16) {
            uint32_t ph4[4], pl4[4];
            ldsm_x4(ph4, sb + SPH + ((wm * 16 + a_row) * EPITCH + kk + a_kof) * 2);
            ldsm_x4(pl4, sb + SPL + ((wm * 16 + a_row) * EPITCH + kk + a_kof) * 2);
            #pragma unroll
            for (int np = 0; np < 4; np++) {
                uint32_t bh4[4], bl4[4];
                ldsm_x4(bh4, vhb + ((np * 16 + b_nof) * EPITCH + kk + b_kof) * 2);
                ldsm_x4(bl4, vlb + ((np * 16 + b_nof) * EPITCH + kk + b_kof) * 2);
                #pragma unroll
                for (int t2 = 0; t2 < 2; t2++) {
                    float* cc = oacc[np * 2 + t2];
                    mma16816(cc, ph4, &bh4[t2 * 2]);
                    mma16816(cc, ph4, &bl4[t2 * 2]);
                    mma16816(cc, pl4, &bh4[t2 * 2]);
                }
            }
        }
    }

    // ---- finalize: quad-reduce row sums, normalize, store ----
    rs0 += __shfl_xor_sync(0xFFFFFFFFu, rs0, 1);
    rs0 += __shfl_xor_sync(0xFFFFFFFFu, rs0, 2);
    rs1 += __shfl_xor_sync(0xFFFFFFFFu, rs1, 1);
    rs1 += __shfl_xor_sync(0xFFFFFFFFu, rs1, 2);
    float inv0 = 1.0f / (1e-8f + rs0);
    float inv1 = 1.0f / (1e-8f + rs1);

    int i0 = wm * 16 + g;
    #pragma unroll
    for (int nt = 0; nt < 8; nt++) {
        int d = nt * 8 + t * 2;
        float2 o0, o1;
        o0.x = oacc[nt][0] * inv0;
        o0.y = oacc[nt][1] * inv0;
        o1.x = oacc[nt][2] * inv1;
        o1.y = oacc[nt][3] * inv1;
        *(float2*)&out[(size_t)(b * SS + l0 + i0) * HIDD + h * 64 + d] = o0;
        *(float2*)&out[(size_t)(b * SS + l0 + i0 + 8) * HIDD + h * 64 + d] = o1;
    }
}

extern "C" void kernel_launch(void* const* d_in, const int* in_sizes, int n_in,
                              void* d_out, int out_size)
{
    const float* hs    = (const float*)d_in[0];
    const float* amask = (const float*)d_in[1];
    const int*   skm   = (const int*)  d_in[2];
    const float* Wq    = (const float*)d_in[3];
    const float* bq    = (const float*)d_in[4];
    const float* Wk    = (const float*)d_in[5];
    const float* bk    = (const float*)d_in[6];
    const float* Wv    = (const float*)d_in[7];
    const float* bv    = (const float*)d_in[8];
    const float* E     = (const float*)d_in[9];
    float* out = (float*)d_out;

    cudaFuncSetAttribute(qkv_tc_kernel, cudaFuncAttributeMaxDynamicSharedMemorySize, QSM_BYTES);
    cudaFuncSetAttribute(attn_tc_kernel, cudaFuncAttributeMaxDynamicSharedMemorySize, ASM_BYTES);

    conv_a_kernel<<<4096, 256>>>(hs);
    conv_w_kernel<<<dim3(32, 32, 3), dim3(32, 8)>>>(Wq, Wk, Wv);
    conv_e_kernel<<<128, 256>>>(E);
    conv_mask_kernel<<<16, 256>>>(amask, skm);
    qkv_tc_kernel<<<dim3(32, 24), 256, QSM_BYTES>>>(bq, bk, bv);
    conv_split_kernel<<<dim3(64, 16), 256>>>();
    attn_tc_kernel<<<dim3(8, 16, 4), 256, ASM_BYTES>>>(out);
}

// round 7
// speedup vs baseline: 4.1165x; 1.6631x over previous
#include <cuda_runtime.h>
#include <cuda_bf16.h>
#include <cstdint>
#include <cstddef>

#define BB 4
#define SS 1024
#define HIDD 1024
#define HH 16
#define DD 64

// scratch: q,k,v in [B,H,S,D] layout (fp32, from qkv)
__device__ float g_q[BB*HH*SS*DD];
__device__ float g_k[BB*HH*SS*DD];
__device__ float g_v[BB*HH*SS*DD];

// pre-converted bf16 split operands for qkv GEMM
__device__ __nv_bfloat16 gAh[4096 * 1024];
__device__ __nv_bfloat16 gAl[4096 * 1024];
__device__ __nv_bfloat16 gBh[3 * 1024 * 1024];   // [sel][n][k]
__device__ __nv_bfloat16 gBl[3 * 1024 * 1024];

// bf16 split q/k/v for attention
__device__ __nv_bfloat16 gQh[BB*HH*SS*DD];
__device__ __nv_bfloat16 gQl[BB*HH*SS*DD];
__device__ __nv_bfloat16 gKh[BB*HH*SS*DD];
__device__ __nv_bfloat16 gKl[BB*HH*SS*DD];
__device__ __nv_bfloat16 gVth[BB*HH*DD*SS];      // [bh][d][s] transposed
__device__ __nv_bfloat16 gVtl[BB*HH*DD*SS];
__device__ __nv_bfloat16 gEh[2047 * 64];         // dist_emb bf16 (hi)
__device__ float gWcomb[BB * SS];                // exp(amask)*skim

__device__ __forceinline__ uint32_t smem_u32(const void* p) {
    uint32_t a;
    asm("{ .reg .u64 t; cvta.to.shared.u64 t, %1; cvt.u32.u64 %0, t; }" : "=r"(a) : "l"(p));
    return a;
}
__device__ __forceinline__ void ldsm_x4(uint32_t* r, uint32_t addr) {
    asm volatile("ldmatrix.sync.aligned.m8n8.x4.shared.b16 {%0,%1,%2,%3}, [%4];"
        : "=r"(r[0]), "=r"(r[1]), "=r"(r[2]), "=r"(r[3]) : "r"(addr));
}
__device__ __forceinline__ void mma16816(float* c, const uint32_t* a, const uint32_t* b) {
    asm volatile(
        "mma.sync.aligned.m16n8k16.row.col.f32.bf16.bf16.f32 "
        "{%0,%1,%2,%3}, {%4,%5,%6,%7}, {%8,%9}, {%0,%1,%2,%3};"
        : "+f"(c[0]), "+f"(c[1]), "+f"(c[2]), "+f"(c[3])
        : "r"(a[0]), "r"(a[1]), "r"(a[2]), "r"(a[3]), "r"(b[0]), "r"(b[1]));
}
__device__ __forceinline__ void cp16(uint32_t dst, const void* src) {
    asm volatile("cp.async.cg.shared.global [%0], [%1], 16;" :: "r"(dst), "l"(src));
}
#define CP_COMMIT() asm volatile("cp.async.commit_group;" ::: "memory")
#define CP_WAIT(N)  asm volatile("cp.async.wait_group %0;" :: "n"(N) : "memory")

__device__ __forceinline__ void split_bf16(float v, __nv_bfloat16& h, __nv_bfloat16& l) {
    h = __float2bfloat16_rn(v);
    l = __float2bfloat16_rn(v - __bfloat162float(h));
}

// ---------------------------------------------------------------------------
// conv kernels (unchanged)
// ---------------------------------------------------------------------------
__global__ __launch_bounds__(256) void conv_a_kernel(const float* __restrict__ A)
{
    int idx = blockIdx.x * 256 + threadIdx.x;
    float4 a4 = *(const float4*)&A[(size_t)idx * 4];
    __nv_bfloat16 h[4], l[4];
    split_bf16(a4.x, h[0], l[0]);
    split_bf16(a4.y, h[1], l[1]);
    split_bf16(a4.z, h[2], l[2]);
    split_bf16(a4.w, h[3], l[3]);
    *(uint2*)&gAh[(size_t)idx * 4] = *(uint2*)h;
    *(uint2*)&gAl[(size_t)idx * 4] = *(uint2*)l;
}

__global__ __launch_bounds__(256) void conv_w_kernel(
    const float* __restrict__ Wq, const float* __restrict__ Wk, const float* __restrict__ Wv)
{
    __shared__ float t[32][33];
    int sel = blockIdx.z;
    const float* W = (sel == 0) ? Wq : (sel == 1) ? Wk : Wv;
    int n0 = blockIdx.x * 32, k0 = blockIdx.y * 32;
    int tx = threadIdx.x, ty = threadIdx.y;

    #pragma unroll
    for (int r = ty; r < 32; r += 8)
        t[r][tx] = W[(size_t)(k0 + r) * HIDD + n0 + tx];
    __syncthreads();
    size_t base = (size_t)sel * 1024 * 1024;
    #pragma unroll
    for (int r = ty; r < 32; r += 8) {
        float v = t[tx][r];
        __nv_bfloat16 h, l;
        split_bf16(v, h, l);
        gBh[base + (size_t)(n0 + r) * 1024 + k0 + tx] = h;
        gBl[base + (size_t)(n0 + r) * 1024 + k0 + tx] = l;
    }
}

__global__ __launch_bounds__(256) void conv_e_kernel(const float* __restrict__ E)
{
    int i4 = blockIdx.x * 256 + threadIdx.x;
    if (i4 < 2047 * 16) {
        float4 a4 = *(const float4*)&E[(size_t)i4 * 4];
        __nv_bfloat16 h[4];
        h[0] = __float2bfloat16_rn(a4.x);
        h[1] = __float2bfloat16_rn(a4.y);
        h[2] = __float2bfloat16_rn(a4.z);
        h[3] = __float2bfloat16_rn(a4.w);
        *(uint2*)&gEh[(size_t)i4 * 4] = *(uint2*)h;
    }
}

__global__ __launch_bounds__(256) void conv_mask_kernel(
    const float* __restrict__ am, const int* __restrict__ sk)
{
    int i = blockIdx.x * 256 + threadIdx.x;
    gWcomb[i] = __expf(am[i]) * (float)sk[i];
}

// ---------------------------------------------------------------------------
// QKV GEMM (unchanged, proven): writes fp32 g_q/g_k/g_v
// ---------------------------------------------------------------------------
#define APITCH 40
#define TILE_B (128 * APITCH * 2)
#define STAGE_B (4 * TILE_B)
#define QSM_BYTES (2 * STAGE_B)

__global__ __launch_bounds__(256, 2) void qkv_tc_kernel(
    const float* __restrict__ bq, const float* __restrict__ bk, const float* __restrict__ bv)
{
    extern __shared__ char smc[];
    uint32_t sb = smem_u32(smc);

    int tid  = threadIdx.x;
    int wid  = tid >> 5;
    int lane = tid & 31;
    int wm = wid & 3;
    int wn = wid >> 2;

    int m0  = blockIdx.x * 128;
    int ng0 = blockIdx.y * 128;
    int sel = ng0 >> 10;
    int n0  = ng0 & 1023;

    const float* bias = (sel == 0) ? bq : (sel == 1) ? bk : bv;
    float* outm       = (sel == 0) ? g_q : (sel == 1) ? g_k : g_v;

    const __nv_bfloat16* pAh = gAh + (size_t)m0 * 1024;
    const __nv_bfloat16* pAl = gAl + (size_t)m0 * 1024;
    const __nv_bfloat16* pBh = gBh + (size_t)sel * 1048576 + (size_t)n0 * 1024;
    const __nv_bfloat16* pBl = gBl + (size_t)sel * 1048576 + (size_t)n0 * 1024;

    auto copy_stage = [&](int s, int buf) {
        int k0 = s * 32;
        uint32_t bbase = sb + buf * STAGE_B;
        #pragma unroll
        for (int p = 0; p < 8; p++) {
            int tile = p >> 1;
            int cidx = tid + (p & 1) * 256;
            int row = cidx >> 2, ch = cidx & 3;
            const __nv_bfloat16* src =
                (tile == 0) ? pAh : (tile == 1) ? pAl : (tile == 2) ? pBh : pBl;
            cp16(bbase + tile * TILE_B + row * (APITCH * 2) + ch * 16,
                 src + (size_t)row * 1024 + k0 + ch * 8);
        }
        CP_COMMIT();
    };

    float acc[2][8][4] = {};

    int a_row = (lane & 15);
    int a_kof = (lane >> 4) * 8;
    int b_nof = (lane & 7) | ((lane >> 4) << 3);
    int b_kof = ((lane >> 3) & 1) * 8;

    copy_stage(0, 0);

    for (int s = 0; s < 32; s++) {
        int buf = s & 1;
        if (s + 1 < 32) {
            copy_stage(s + 1, buf ^ 1);
            CP_WAIT(1);
        } else {
            CP_WAIT(0);
        }
        __syncthreads();

        uint32_t bAh = sb + buf * STAGE_B;
        uint32_t bAl = bAh + TILE_B;
        uint32_t bBh = bAl + TILE_B;
        uint32_t bBl = bBh + TILE_B;

        #pragma unroll
        for (int kk = 0; kk < 32; kk += 16) {
            uint32_t ah[2][4], al[2][4];
            #pragma unroll
            for (int mt = 0; mt < 2; mt++) {
                int off = ((wm * 32 + mt * 16 + a_row) * APITCH + kk + a_kof) * 2;
                ldsm_x4(ah[mt], bAh + off);
                ldsm_x4(al[mt], bAl + off);
            }
            #pragma unroll
            for (int np = 0; np < 4; np++) {
                uint32_t bh4[4], bl4[4];
                int off = ((wn * 64 + np * 16 + b_nof) * APITCH + kk + b_kof) * 2;
                ldsm_x4(bh4, bBh + off);
                ldsm_x4(bl4, bBl + off);
                #pragma unroll
                for (int mt = 0; mt < 2; mt++)
                    #pragma unroll
                    for (int t = 0; t < 2; t++) {
                        float* c = acc[mt][np * 2 + t];
                        mma16816(c, ah[mt], &bh4[t * 2]);
                        mma16816(c, ah[mt], &bl4[t * 2]);
                        mma16816(c, al[mt], &bh4[t * 2]);
                    }
            }
        }
        __syncthreads();
    }

    int g = lane >> 2, t = lane & 3;
    #pragma unroll
    for (int nt = 0; nt < 8; nt++) {
        int nc = n0 + wn * 64 + nt * 8 + t * 2;
        int h_ = nc >> 6, d = nc & 63;
        float b0 = bias[nc], b1 = bias[nc + 1];
        #pragma unroll
        for (int mt = 0; mt < 2; mt++) {
            #pragma unroll
            for (int half = 0; half < 2; half++) {
                int m = m0 + wm * 32 + mt * 16 + g + half * 8;
                int b_ = m >> 10, s_ = m & 1023;
                float2 o;
                o.x = acc[mt][nt][half * 2 + 0] + b0;
                o.y = acc[mt][nt][half * 2 + 1] + b1;
                *(float2*)&outm[((size_t)(b_ * HH + h_) * SS + s_) * DD + d] = o;
            }
        }
    }
}

// ---------------------------------------------------------------------------
// conv_split: fp32 q/k/v -> bf16 split; v transposed to [bh][d][s].
// ---------------------------------------------------------------------------
__global__ __launch_bounds__(256) void conv_split_kernel()
{
    __shared__ float vt[64][65];
    int bh = blockIdx.x;
    int s0 = blockIdx.y * 64;
    int tid = threadIdx.x;
    size_t base = (size_t)bh * SS * DD + (size_t)s0 * DD;
    const float* q = g_q + base;
    const float* k = g_k + base;
    const float* v = g_v + base;

    #pragma unroll
    for (int p = 0; p < 4; p++) {
        int i4 = tid + p * 256;
        int s_ = i4 >> 4, d4 = (i4 & 15) * 4;
        size_t go = base + (size_t)s_ * 64 + d4;

        float4 a = *(const float4*)&q[(size_t)s_ * 64 + d4];
        __nv_bfloat16 h[4], l[4];
        split_bf16(a.x, h[0], l[0]); split_bf16(a.y, h[1], l[1]);
        split_bf16(a.z, h[2], l[2]); split_bf16(a.w, h[3], l[3]);
        *(uint2*)&gQh[go] = *(uint2*)h;
        *(uint2*)&gQl[go] = *(uint2*)l;

        a = *(const float4*)&k[(size_t)s_ * 64 + d4];
        split_bf16(a.x, h[0], l[0]); split_bf16(a.y, h[1], l[1]);
        split_bf16(a.z, h[2], l[2]); split_bf16(a.w, h[3], l[3]);
        *(uint2*)&gKh[go] = *(uint2*)h;
        *(uint2*)&gKl[go] = *(uint2*)l;

        a = *(const float4*)&v[(size_t)s_ * 64 + d4];
        vt[d4 + 0][s_] = a.x;
        vt[d4 + 1][s_] = a.y;
        vt[d4 + 2][s_] = a.z;
        vt[d4 + 3][s_] = a.w;
    }
    __syncthreads();
    #pragma unroll
    for (int p = 0; p < 4; p++) {
        int i4 = tid + p * 256;
        int d = i4 >> 4, s4 = (i4 & 15) * 4;
        __nv_bfloat16 h[4], l[4];
        split_bf16(vt[d][s4 + 0], h[0], l[0]);
        split_bf16(vt[d][s4 + 1], h[1], l[1]);
        split_bf16(vt[d][s4 + 2], h[2], l[2]);
        split_bf16(vt[d][s4 + 3], h[3], l[3]);
        size_t go = (size_t)bh * DD * SS + (size_t)d * SS + s0 + s4;
        *(uint2*)&gVth[go] = *(uint2*)h;
        *(uint2*)&gVtl[go] = *(uint2*)l;
    }
}

// ---------------------------------------------------------------------------
// attn_tc: 64-query CTA, 2 CTAs/SM. 8 warps = 4(m) x 2(n).
// Per 64-key tile: T = Qh @ E_band^T (hi); S = QK^T (split);
// p = exp((S+T)/8)*w; O += P @ V (split). grid (16, 16, 4).
// ---------------------------------------------------------------------------
#define EPITCH 72      // bf16 elems per smem row (144 B)
#define ROWB 144
#define TP 136         // T pitch (elems)
#define SQH 0
#define SQL 9216
#define SKH 18432      // K hi
#define SKL 27648
#define SVH 36864      // V^T hi
#define SVL 46080
#define SE  55296      // 128 rows x 144 B = 18432
#define ST  73728      // 64 x 136 x 2 = 17408 (reused as reduction buffer)
#define SPH 91136
#define SPL 100352
#define SW  109568     // 1024 floats
#define ASM_BYTES 113664

__global__ __launch_bounds__(256, 2) void attn_tc_kernel(float* __restrict__ out)
{
    extern __shared__ char smc[];
    uint32_t sb = smem_u32(smc);
    int tid = threadIdx.x, wid = tid >> 5, lane = tid & 31;
    int wm = wid & 3, wn = wid >> 2;
    int b = blockIdx.z, h = blockIdx.y;
    int l0 = blockIdx.x * 64;
    int bh = b * HH + h;

    const __nv_bfloat16* pQh = gQh + ((size_t)bh * SS + l0) * DD;
    const __nv_bfloat16* pQl = gQl + ((size_t)bh * SS + l0) * DD;
    const __nv_bfloat16* pKh = gKh + (size_t)bh * SS * DD;
    const __nv_bfloat16* pKl = gKl + (size_t)bh * SS * DD;
    const __nv_bfloat16* pVh = gVth + (size_t)bh * DD * SS;
    const __nv_bfloat16* pVl = gVtl + (size_t)bh * DD * SS;

    int a_row = lane & 15;
    int a_kof = (lane >> 4) * 8;
    int b_nof = (lane & 7) | ((lane >> 4) << 3);
    int b_kof = ((lane >> 3) & 1) * 8;
    int g = lane >> 2, t = lane & 3;

    auto load_kv = [&](int s2) {
        int rr = s2 * 64;
        #pragma unroll
        for (int p = 0; p < 8; p++) {
            int idx = tid + p * 256;
            int arr = idx >> 9, rc = idx & 511;
            int row = rc >> 3, ch = rc & 7;
            const __nv_bfloat16* src =
                (arr == 0) ? pKh + (size_t)(rr + row) * 64 + ch * 8 :
                (arr == 1) ? pKl + (size_t)(rr + row) * 64 + ch * 8 :
                (arr == 2) ? pVh + (size_t)row * SS + rr + ch * 8 :
                             pVl + (size_t)row * SS + rr + ch * 8;
            cp16(sb + SKH + arr * 9216 + row * ROWB + ch * 16, src);
        }
    };
    auto load_e = [&](int s2) {
        int base = l0 - s2 * 64 + 960;
        #pragma unroll
        for (int p = 0; p < 4; p++) {
            int idx = tid + p * 256;
            int row = idx >> 3, ch = idx & 7;
            int er = base + row;
            if (er > 2046) er = 2046;
            cp16(sb + SE + row * ROWB + ch * 16, gEh + (size_t)er * 64 + ch * 8);
        }
    };

    // prologue: Q hi/lo (1024 cps), w (256), KV0 + E0
    #pragma unroll
    for (int p = 0; p < 4; p++) {
        int idx = tid + p * 256;
        int arr = idx >> 9, rc = idx & 511;
        int row = rc >> 3, ch = rc & 7;
        cp16(sb + (arr ? SQL : SQH) + row * ROWB + ch * 16,
             (arr ? pQl : pQh) + (size_t)row * 64 + ch * 8);
    }
    cp16(sb + SW + tid * 16, gWcomb + b * SS + tid * 4);
    load_kv(0);
    load_e(0);
    CP_COMMIT();

    float oacc[4][4] = {};
    float rs0 = 0.f, rs1 = 0.f;
    int i0 = wm * 16 + g, i1 = i0 + 8;

    for (int s = 0; s < 16; s++) {
        int r0 = s * 64;
        CP_WAIT(0);
        __syncthreads();

        // ---- bias GEMM: T[64 x 128] = Qh @ E_band^T (hi only) ----
        {
            float tac[8][4] = {};
            #pragma unroll
            for (int kk = 0; kk < 64; kk += 16) {
                uint32_t ah4[4];
                ldsm_x4(ah4, sb + SQH + ((wm * 16 + a_row) * EPITCH + kk + a_kof) * 2);
                #pragma unroll
                for (int np = 0; np < 4; np++) {
                    uint32_t eb4[4];
                    ldsm_x4(eb4, sb + SE + ((wn * 64 + np * 16 + b_nof) * EPITCH + kk + b_kof) * 2);
                    mma16816(tac[np * 2 + 0], ah4, &eb4[0]);
                    mma16816(tac[np * 2 + 1], ah4, &eb4[2]);
                }
            }
            #pragma unroll
            for (int nt = 0; nt < 8; nt++) {
                int col = wn * 64 + nt * 8 + t * 2;
                __nv_bfloat162 v0, v1;
                v0.x = __float2bfloat16_rn(tac[nt][0]);
                v0.y = __float2bfloat16_rn(tac[nt][1]);
                v1.x = __float2bfloat16_rn(tac[nt][2]);
                v1.y = __float2bfloat16_rn(tac[nt][3]);
                *(__nv_bfloat162*)(smc + ST + (i0 * TP + col) * 2) = v0;
                *(__nv_bfloat162*)(smc + ST + (i1 * TP + col) * 2) = v1;
            }
        }
        __syncthreads();   // T visible; E consumed

        // E buffer free now — prefetch next E early
        if (s + 1 < 16) {
            load_e(s + 1);
            CP_COMMIT();
        }

        // ---- QK^T (split precision), warp cols wn*32..+32 ----
        float sac[4][4] = {};
        #pragma unroll
        for (int kk = 0; kk < 64; kk += 16) {
            uint32_t ah4[4], al4[4];
            ldsm_x4(ah4, sb + SQH + ((wm * 16 + a_row) * EPITCH + kk + a_kof) * 2);
            ldsm_x4(al4, sb + SQL + ((wm * 16 + a_row) * EPITCH + kk + a_kof) * 2);
            #pragma unroll
            for (int np = 0; np < 2; np++) {
                uint32_t bh4[4], bl4[4];
                int roff = ((wn * 32 + np * 16 + b_nof) * EPITCH + kk + b_kof) * 2;
                ldsm_x4(bh4, sb + SKH + roff);
                ldsm_x4(bl4, sb + SKL + roff);
                #pragma unroll
                for (int t2 = 0; t2 < 2; t2++) {
                    float* cc = sac[np * 2 + t2];
                    mma16816(cc, ah4, &bh4[t2 * 2]);
                    mma16816(cc, ah4, &bl4[t2 * 2]);
                    mma16816(cc, al4, &bh4[t2 * 2]);
                }
            }
        }

        // ---- epilogue: gather T, exp, split P ----
        #pragma unroll
        for (int nt = 0; nt < 4; nt++) {
            int j = wn * 32 + nt * 8 + t * 2;
            float w0 = *(const float*)(smc + SW + (r0 + j) * 4);
            float w1 = *(const float*)(smc + SW + (r0 + j + 1) * 4);
            int jj0 = i0 - j + 63;
            int jj1 = i1 - j + 63;
            float t00 = __bfloat162float(*(const __nv_bfloat16*)(smc + ST + (i0 * TP + jj0) * 2));
            float t01 = __bfloat162float(*(const __nv_bfloat16*)(smc + ST + (i0 * TP + jj0 - 1) * 2));
            float t10 = __bfloat162float(*(const __nv_bfloat16*)(smc + ST + (i1 * TP + jj1) * 2));
            float t11 = __bfloat162float(*(const __nv_bfloat16*)(smc + ST + (i1 * TP + jj1 - 1) * 2));
            float p0 = __expf((sac[nt][0] + t00) * 0.125f) * w0;
            float p1 = __expf((sac[nt][1] + t01) * 0.125f) * w1;
            float p2 = __expf((sac[nt][2] + t10) * 0.125f) * w0;
            float p3 = __expf((sac[nt][3] + t11) * 0.125f) * w1;
            rs0 += p0 + p1;
            rs1 += p2 + p3;
            __nv_bfloat162 ph0, pl0, ph1, pl1;
            split_bf16(p0, ph0.x, pl0.x);
            split_bf16(p1, ph0.y, pl0.y);
            split_bf16(p2, ph1.x, pl1.x);
            split_bf16(p3, ph1.y, pl1.y);
            *(__nv_bfloat162*)(smc + SPH + (i0 * EPITCH + j) * 2) = ph0;
            *(__nv_bfloat162*)(smc + SPL + (i0 * EPITCH + j) * 2) = pl0;
            *(__nv_bfloat162*)(smc + SPH + (i1 * EPITCH + j) * 2) = ph1;
            *(__nv_bfloat162*)(smc + SPL + (i1 * EPITCH + j) * 2) = pl1;
        }
        __syncthreads();   // P cross-warp (wn pair shares rows)

        // ---- PV (split precision), warp cols wn*32..+32 of D ----
        #pragma unroll
        for (int kk = 0; kk < 64; kk += 16) {
            uint32_t ph4[4], pl4[4];
            ldsm_x4(ph4, sb + SPH + ((wm * 16 + a_row) * EPITCH + kk + a_kof) * 2);
            ldsm_x4(pl4, sb + SPL + ((wm * 16 + a_row) * EPITCH + kk + a_kof) * 2);
            #pragma unroll
            for (int np = 0; np < 2; np++) {
                uint32_t bh4[4], bl4[4];
                int roff = ((wn * 32 + np * 16 + b_nof) * EPITCH + kk + b_kof) * 2;
                ldsm_x4(bh4, sb + SVH + roff);
                ldsm_x4(bl4, sb + SVL + roff);
                #pragma unroll
                for (int t2 = 0; t2 < 2; t2++) {
                    float* cc = oacc[np * 2 + t2];
                    mma16816(cc, ph4, &bh4[t2 * 2]);
                    mma16816(cc, ph4, &bl4[t2 * 2]);
                    mma16816(cc, pl4, &bh4[t2 * 2]);
                }
            }
        }
        __syncthreads();   // KV/E/T consumed; safe to overwrite

        if (s + 1 < 16) {
            load_kv(s + 1);
            CP_COMMIT();
        }
    }

    // ---- finalize: quad + cross-wn reduce of row sums, normalize, store ----
    rs0 += __shfl_xor_sync(0xFFFFFFFFu, rs0, 1);
    rs0 += __shfl_xor_sync(0xFFFFFFFFu, rs0, 2);
    rs1 += __shfl_xor_sync(0xFFFFFFFFu, rs1, 1);
    rs1 += __shfl_xor_sync(0xFFFFFFFFu, rs1, 2);

    float* red = (float*)(smc + ST);   // reuse T region: [64][2]
    red[i0 * 2 + wn] = rs0;
    red[i1 * 2 + wn] = rs1;
    __syncthreads();
    float inv0 = 1.0f / (1e-8f + red[i0 * 2] + red[i0 * 2 + 1]);
    float inv1 = 1.0f / (1e-8f + red[i1 * 2] + red[i1 * 2 + 1]);

    #pragma unroll
    for (int nt = 0; nt < 4; nt++) {
        int d = wn * 32 + nt * 8 + t * 2;
        float2 o0, o1;
        o0.x = oacc[nt][0] * inv0;
        o0.y = oacc[nt][1] * inv0;
        o1.x = oacc[nt][2] * inv1;
        o1.y = oacc[nt][3] * inv1;
        *(float2*)&out[(size_t)(b * SS + l0 + i0) * HIDD + h * 64 + d] = o0;
        *(float2*)&out[(size_t)(b * SS + l0 + i1) * HIDD + h * 64 + d] = o1;
    }
}

extern "C" void kernel_launch(void* const* d_in, const int* in_sizes, int n_in,
                              void* d_out, int out_size)
{
    const float* hs    = (const float*)d_in[0];
    const float* amask = (const float*)d_in[1];
    const int*   skm   = (const int*)  d_in[2];
    const float* Wq    = (const float*)d_in[3];
    const float* bq    = (const float*)d_in[4];
    const float* Wk    = (const float*)d_in[5];
    const float* bk    = (const float*)d_in[6];
    const float* Wv    = (const float*)d_in[7];
    const float* bv    = (const float*)d_in[8];
    const float* E     = (const float*)d_in[9];
    float* out = (float*)d_out;

    cudaFuncSetAttribute(qkv_tc_kernel, cudaFuncAttributeMaxDynamicSharedMemorySize, QSM_BYTES);
    cudaFuncSetAttribute(attn_tc_kernel, cudaFuncAttributeMaxDynamicSharedMemorySize, ASM_BYTES);

    conv_a_kernel<<<4096, 256>>>(hs);
    conv_w_kernel<<<dim3(32, 32, 3), dim3(32, 8)>>>(Wq, Wk, Wv);
    conv_e_kernel<<<128, 256>>>(E);
    conv_mask_kernel<<<16, 256>>>(amask, skm);
    qkv_tc_kernel<<<dim3(32, 24), 256, QSM_BYTES>>>(bq, bk, bv);
    conv_split_kernel<<<dim3(64, 16), 256>>>();
    attn_tc_kernel<<<dim3(16, 16, 4), 256, ASM_BYTES>>>(out);
}

// round 8
// speedup vs baseline: 4.3006x; 1.0447x over previous
#include <cuda_runtime.h>
#include <cuda_bf16.h>
#include <cstdint>
#include <cstddef>

#define BB 4
#define SS 1024
#define HIDD 1024
#define HH 16
#define DD 64

// fp32 scratch: only V needs it now (for the transpose pass)
__device__ float g_v[BB*HH*SS*DD];

// pre-converted bf16 split operands for qkv GEMM
__device__ __nv_bfloat16 gAh[4096 * 1024];
__device__ __nv_bfloat16 gAl[4096 * 1024];
__device__ __nv_bfloat16 gBh[3 * 1024 * 1024];   // [sel][n][k]
__device__ __nv_bfloat16 gBl[3 * 1024 * 1024];

// bf16 split q/k/v for attention
__device__ __nv_bfloat16 gQh[BB*HH*SS*DD];
__device__ __nv_bfloat16 gQl[BB*HH*SS*DD];
__device__ __nv_bfloat16 gKh[BB*HH*SS*DD];
__device__ __nv_bfloat16 gKl[BB*HH*SS*DD];
__device__ __nv_bfloat16 gVth[BB*HH*DD*SS];      // [bh][d][s] transposed
__device__ __nv_bfloat16 gVtl[BB*HH*DD*SS];
__device__ __nv_bfloat16 gEh[2047 * 64];         // dist_emb bf16 (hi)
__device__ float gWcomb[BB * SS];                // exp(amask)*skim

__device__ __forceinline__ uint32_t smem_u32(const void* p) {
    uint32_t a;
    asm("{ .reg .u64 t; cvta.to.shared.u64 t, %1; cvt.u32.u64 %0, t; }" : "=r"(a) : "l"(p));
    return a;
}
__device__ __forceinline__ void ldsm_x4(uint32_t* r, uint32_t addr) {
    asm volatile("ldmatrix.sync.aligned.m8n8.x4.shared.b16 {%0,%1,%2,%3}, [%4];"
        : "=r"(r[0]), "=r"(r[1]), "=r"(r[2]), "=r"(r[3]) : "r"(addr));
}
__device__ __forceinline__ void mma16816(float* c, const uint32_t* a, const uint32_t* b) {
    asm volatile(
        "mma.sync.aligned.m16n8k16.row.col.f32.bf16.bf16.f32 "
        "{%0,%1,%2,%3}, {%4,%5,%6,%7}, {%8,%9}, {%0,%1,%2,%3};"
        : "+f"(c[0]), "+f"(c[1]), "+f"(c[2]), "+f"(c[3])
        : "r"(a[0]), "r"(a[1]), "r"(a[2]), "r"(a[3]), "r"(b[0]), "r"(b[1]));
}
__device__ __forceinline__ void cp16(uint32_t dst, const void* src) {
    asm volatile("cp.async.cg.shared.global [%0], [%1], 16;" :: "r"(dst), "l"(src));
}
#define CP_COMMIT() asm volatile("cp.async.commit_group;" ::: "memory")
#define CP_WAIT(N)  asm volatile("cp.async.wait_group %0;" :: "n"(N) : "memory")

__device__ __forceinline__ void split_bf16(float v, __nv_bfloat16& h, __nv_bfloat16& l) {
    h = __float2bfloat16_rn(v);
    l = __float2bfloat16_rn(v - __bfloat162float(h));
}

// ---------------------------------------------------------------------------
// conv kernels
// ---------------------------------------------------------------------------
__global__ __launch_bounds__(256) void conv_a_kernel(const float* __restrict__ A)
{
    int idx = blockIdx.x * 256 + threadIdx.x;
    float4 a4 = *(const float4*)&A[(size_t)idx * 4];
    __nv_bfloat16 h[4], l[4];
    split_bf16(a4.x, h[0], l[0]);
    split_bf16(a4.y, h[1], l[1]);
    split_bf16(a4.z, h[2], l[2]);
    split_bf16(a4.w, h[3], l[3]);
    *(uint2*)&gAh[(size_t)idx * 4] = *(uint2*)h;
    *(uint2*)&gAl[(size_t)idx * 4] = *(uint2*)l;
}

__global__ __launch_bounds__(256) void conv_w_kernel(
    const float* __restrict__ Wq, const float* __restrict__ Wk, const float* __restrict__ Wv)
{
    __shared__ float t[32][33];
    int sel = blockIdx.z;
    const float* W = (sel == 0) ? Wq : (sel == 1) ? Wk : Wv;
    int n0 = blockIdx.x * 32, k0 = blockIdx.y * 32;
    int tx = threadIdx.x, ty = threadIdx.y;

    #pragma unroll
    for (int r = ty; r < 32; r += 8)
        t[r][tx] = W[(size_t)(k0 + r) * HIDD + n0 + tx];
    __syncthreads();
    size_t base = (size_t)sel * 1024 * 1024;
    #pragma unroll
    for (int r = ty; r < 32; r += 8) {
        float v = t[tx][r];
        __nv_bfloat16 h, l;
        split_bf16(v, h, l);
        gBh[base + (size_t)(n0 + r) * 1024 + k0 + tx] = h;
        gBl[base + (size_t)(n0 + r) * 1024 + k0 + tx] = l;
    }
}

__global__ __launch_bounds__(256) void conv_e_kernel(const float* __restrict__ E)
{
    int i4 = blockIdx.x * 256 + threadIdx.x;
    if (i4 < 2047 * 16) {
        float4 a4 = *(const float4*)&E[(size_t)i4 * 4];
        __nv_bfloat16 h[4];
        h[0] = __float2bfloat16_rn(a4.x);
        h[1] = __float2bfloat16_rn(a4.y);
        h[2] = __float2bfloat16_rn(a4.z);
        h[3] = __float2bfloat16_rn(a4.w);
        *(uint2*)&gEh[(size_t)i4 * 4] = *(uint2*)h;
    }
}

__global__ __launch_bounds__(256) void conv_mask_kernel(
    const float* __restrict__ am, const int* __restrict__ sk)
{
    int i = blockIdx.x * 256 + threadIdx.x;
    gWcomb[i] = __expf(am[i]) * (float)sk[i];
}

// ---------------------------------------------------------------------------
// QKV GEMM: mainloop unchanged (proven). Epilogue: Q/K written as split bf16
// directly; V written fp32 (transposed+split by conv_splitv).
// ---------------------------------------------------------------------------
#define APITCH 40
#define TILE_B (128 * APITCH * 2)
#define STAGE_B (4 * TILE_B)
#define QSM_BYTES (2 * STAGE_B)

__global__ __launch_bounds__(256, 2) void qkv_tc_kernel(
    const float* __restrict__ bq, const float* __restrict__ bk, const float* __restrict__ bv)
{
    extern __shared__ char smc[];
    uint32_t sb = smem_u32(smc);

    int tid  = threadIdx.x;
    int wid  = tid >> 5;
    int lane = tid & 31;
    int wm = wid & 3;
    int wn = wid >> 2;

    int m0  = blockIdx.x * 128;
    int ng0 = blockIdx.y * 128;
    int sel = ng0 >> 10;
    int n0  = ng0 & 1023;

    const float* bias = (sel == 0) ? bq : (sel == 1) ? bk : bv;

    const __nv_bfloat16* pAh = gAh + (size_t)m0 * 1024;
    const __nv_bfloat16* pAl = gAl + (size_t)m0 * 1024;
    const __nv_bfloat16* pBh = gBh + (size_t)sel * 1048576 + (size_t)n0 * 1024;
    const __nv_bfloat16* pBl = gBl + (size_t)sel * 1048576 + (size_t)n0 * 1024;

    auto copy_stage = [&](int s, int buf) {
        int k0 = s * 32;
        uint32_t bbase = sb + buf * STAGE_B;
        #pragma unroll
        for (int p = 0; p < 8; p++) {
            int tile = p >> 1;
            int cidx = tid + (p & 1) * 256;
            int row = cidx >> 2, ch = cidx & 3;
            const __nv_bfloat16* src =
                (tile == 0) ? pAh : (tile == 1) ? pAl : (tile == 2) ? pBh : pBl;
            cp16(bbase + tile * TILE_B + row * (APITCH * 2) + ch * 16,
                 src + (size_t)row * 1024 + k0 + ch * 8);
        }
        CP_COMMIT();
    };

    float acc[2][8][4] = {};

    int a_row = (lane & 15);
    int a_kof = (lane >> 4) * 8;
    int b_nof = (lane & 7) | ((lane >> 4) << 3);
    int b_kof = ((lane >> 3) & 1) * 8;

    copy_stage(0, 0);

    for (int s = 0; s < 32; s++) {
        int buf = s & 1;
        if (s + 1 < 32) {
            copy_stage(s + 1, buf ^ 1);
            CP_WAIT(1);
        } else {
            CP_WAIT(0);
        }
        __syncthreads();

        uint32_t bAh = sb + buf * STAGE_B;
        uint32_t bAl = bAh + TILE_B;
        uint32_t bBh = bAl + TILE_B;
        uint32_t bBl = bBh + TILE_B;

        #pragma unroll
        for (int kk = 0; kk < 32; kk += 16) {
            uint32_t ah[2][4], al[2][4];
            #pragma unroll
            for (int mt = 0; mt < 2; mt++) {
                int off = ((wm * 32 + mt * 16 + a_row) * APITCH + kk + a_kof) * 2;
                ldsm_x4(ah[mt], bAh + off);
                ldsm_x4(al[mt], bAl + off);
            }
            #pragma unroll
            for (int np = 0; np < 4; np++) {
                uint32_t bh4[4], bl4[4];
                int off = ((wn * 64 + np * 16 + b_nof) * APITCH + kk + b_kof) * 2;
                ldsm_x4(bh4, bBh + off);
                ldsm_x4(bl4, bBl + off);
                #pragma unroll
                for (int mt = 0; mt < 2; mt++)
                    #pragma unroll
                    for (int t = 0; t < 2; t++) {
                        float* c = acc[mt][np * 2 + t];
                        mma16816(c, ah[mt], &bh4[t * 2]);
                        mma16816(c, ah[mt], &bl4[t * 2]);
                        mma16816(c, al[mt], &bh4[t * 2]);
                    }
            }
        }
        __syncthreads();
    }

    int g = lane >> 2, t = lane & 3;
    #pragma unroll
    for (int nt = 0; nt < 8; nt++) {
        int nc = n0 + wn * 64 + nt * 8 + t * 2;
        int h_ = nc >> 6, d = nc & 63;
        float b0 = bias[nc], b1 = bias[nc + 1];
        #pragma unroll
        for (int mt = 0; mt < 2; mt++) {
            #pragma unroll
            for (int half = 0; half < 2; half++) {
                int m = m0 + wm * 32 + mt * 16 + g + half * 8;
                int b_ = m >> 10, s_ = m & 1023;
                float vx = acc[mt][nt][half * 2 + 0] + b0;
                float vy = acc[mt][nt][half * 2 + 1] + b1;
                size_t off = ((size_t)(b_ * HH + h_) * SS + s_) * DD + d;
                if (sel == 2) {
                    float2 o; o.x = vx; o.y = vy;
                    *(float2*)&g_v[off] = o;
                } else {
                    __nv_bfloat162 oh, ol;
                    split_bf16(vx, oh.x, ol.x);
                    split_bf16(vy, oh.y, ol.y);
                    if (sel == 0) {
                        *(__nv_bfloat162*)&gQh[off] = oh;
                        *(__nv_bfloat162*)&gQl[off] = ol;
                    } else {
                        *(__nv_bfloat162*)&gKh[off] = oh;
                        *(__nv_bfloat162*)&gKl[off] = ol;
                    }
                }
            }
        }
    }
}

// ---------------------------------------------------------------------------
// conv_splitv: fp32 V -> bf16 split, transposed to [bh][d][s].
// ---------------------------------------------------------------------------
__global__ __launch_bounds__(256) void conv_splitv_kernel()
{
    __shared__ float vt[64][65];
    int bh = blockIdx.x;
    int s0 = blockIdx.y * 64;
    int tid = threadIdx.x;
    const float* v = g_v + (size_t)bh * SS * DD + (size_t)s0 * DD;

    #pragma unroll
    for (int p = 0; p < 4; p++) {
        int i4 = tid + p * 256;
        int s_ = i4 >> 4, d4 = (i4 & 15) * 4;
        float4 a = *(const float4*)&v[(size_t)s_ * 64 + d4];
        vt[d4 + 0][s_] = a.x;
        vt[d4 + 1][s_] = a.y;
        vt[d4 + 2][s_] = a.z;
        vt[d4 + 3][s_] = a.w;
    }
    __syncthreads();
    #pragma unroll
    for (int p = 0; p < 4; p++) {
        int i4 = tid + p * 256;
        int d = i4 >> 4, s4 = (i4 & 15) * 4;
        __nv_bfloat16 h[4], l[4];
        split_bf16(vt[d][s4 + 0], h[0], l[0]);
        split_bf16(vt[d][s4 + 1], h[1], l[1]);
        split_bf16(vt[d][s4 + 2], h[2], l[2]);
        split_bf16(vt[d][s4 + 3], h[3], l[3]);
        size_t go = (size_t)bh * DD * SS + (size_t)d * SS + s0 + s4;
        *(uint2*)&gVth[go] = *(uint2*)h;
        *(uint2*)&gVtl[go] = *(uint2*)l;
    }
}

// ---------------------------------------------------------------------------
// attn_tc: 64-query CTA, 2 CTAs/SM, 8 warps = 4(m) x 2(n).
// Staggered 3-group cp.async pipeline (E/K/V), 3 syncs per tile.
// grid (16, 16, 4).
// ---------------------------------------------------------------------------
#define EPITCH 72
#define ROWB 144
#define TP 136
#define SQH 0
#define SQL 9216
#define SKH 18432
#define SKL 27648
#define SVH 36864
#define SVL 46080
#define SE  55296
#define ST  73728
#define SPH 91136
#define SPL 100352
#define SW  109568
#define ASM_BYTES 113664

__global__ __launch_bounds__(256, 2) void attn_tc_kernel(float* __restrict__ out)
{
    extern __shared__ char smc[];
    uint32_t sb = smem_u32(smc);
    int tid = threadIdx.x, wid = tid >> 5, lane = tid & 31;
    int wm = wid & 3, wn = wid >> 2;
    int b = blockIdx.z, h = blockIdx.y;
    int l0 = blockIdx.x * 64;
    int bh = b * HH + h;

    const __nv_bfloat16* pQh = gQh + ((size_t)bh * SS + l0) * DD;
    const __nv_bfloat16* pQl = gQl + ((size_t)bh * SS + l0) * DD;
    const __nv_bfloat16* pKh = gKh + (size_t)bh * SS * DD;
    const __nv_bfloat16* pKl = gKl + (size_t)bh * SS * DD;
    const __nv_bfloat16* pVh = gVth + (size_t)bh * DD * SS;
    const __nv_bfloat16* pVl = gVtl + (size_t)bh * DD * SS;

    int a_row = lane & 15;
    int a_kof = (lane >> 4) * 8;
    int b_nof = (lane & 7) | ((lane >> 4) << 3);
    int b_kof = ((lane >> 3) & 1) * 8;
    int g = lane >> 2, t = lane & 3;

    auto load_k = [&](int s2) {
        int rr = s2 * 64;
        #pragma unroll
        for (int p = 0; p < 4; p++) {
            int idx = tid + p * 256;
            int arr = idx >> 9, rc = idx & 511;
            int row = rc >> 3, ch = rc & 7;
            const __nv_bfloat16* src = (arr == 0)
                ? pKh + (size_t)(rr + row) * 64 + ch * 8
                : pKl + (size_t)(rr + row) * 64 + ch * 8;
            cp16(sb + SKH + arr * 9216 + row * ROWB + ch * 16, src);
        }
    };
    auto load_v = [&](int s2) {
        int rr = s2 * 64;
        #pragma unroll
        for (int p = 0; p < 4; p++) {
            int idx = tid + p * 256;
            int arr = idx >> 9, rc = idx & 511;
            int row = rc >> 3, ch = rc & 7;
            const __nv_bfloat16* src = (arr == 0)
                ? pVh + (size_t)row * SS + rr + ch * 8
                : pVl + (size_t)row * SS + rr + ch * 8;
            cp16(sb + SVH + arr * 9216 + row * ROWB + ch * 16, src);
        }
    };
    auto load_e = [&](int s2) {
        int base = l0 - s2 * 64 + 960;
        #pragma unroll
        for (int p = 0; p < 4; p++) {
            int idx = tid + p * 256;
            int row = idx >> 3, ch = idx & 7;
            int er = base + row;
            if (er > 2046) er = 2046;
            cp16(sb + SE + row * ROWB + ch * 16, gEh + (size_t)er * 64 + ch * 8);
        }
    };

    // prologue: group1 = Q + w + E0, group2 = K0, group3 = V0
    #pragma unroll
    for (int p = 0; p < 4; p++) {
        int idx = tid + p * 256;
        int arr = idx >> 9, rc = idx & 511;
        int row = rc >> 3, ch = rc & 7;
        cp16(sb + (arr ? SQL : SQH) + row * ROWB + ch * 16,
             (arr ? pQl : pQh) + (size_t)row * 64 + ch * 8);
    }
    cp16(sb + SW + tid * 16, gWcomb + b * SS + tid * 4);
    load_e(0);
    CP_COMMIT();
    load_k(0);
    CP_COMMIT();
    load_v(0);
    CP_COMMIT();

    CP_WAIT(2);          // Q, w, E0 ready
    __syncthreads();

    float oacc[4][4] = {};
    float rs0 = 0.f, rs1 = 0.f;
    int i0 = wm * 16 + g, i1 = i0 + 8;

    for (int s = 0; s < 16; s++) {
        int r0 = s * 64;

        // ---- phase 1: bias GEMM T[64x128] = Qh @ E_band^T ----
        {
            float tac[8][4] = {};
            #pragma unroll
            for (int kk = 0; kk < 64; kk += 16) {
                uint32_t ah4[4];
                ldsm_x4(ah4, sb + SQH + ((wm * 16 + a_row) * EPITCH + kk + a_kof) * 2);
                #pragma unroll
                for (int np = 0; np < 4; np++) {
                    uint32_t eb4[4];
                    ldsm_x4(eb4, sb + SE + ((wn * 64 + np * 16 + b_nof) * EPITCH + kk + b_kof) * 2);
                    mma16816(tac[np * 2 + 0], ah4, &eb4[0]);
                    mma16816(tac[np * 2 + 1], ah4, &eb4[2]);
                }
            }
            #pragma unroll
            for (int nt = 0; nt < 8; nt++) {
                int col = wn * 64 + nt * 8 + t * 2;
                __nv_bfloat162 v0, v1;
                v0.x = __float2bfloat16_rn(tac[nt][0]);
                v0.y = __float2bfloat16_rn(tac[nt][1]);
                v1.x = __float2bfloat16_rn(tac[nt][2]);
                v1.y = __float2bfloat16_rn(tac[nt][3]);
                *(__nv_bfloat162*)(smc + ST + (i0 * TP + col) * 2) = v0;
                *(__nv_bfloat162*)(smc + ST + (i1 * TP + col) * 2) = v1;
            }
        }
        CP_WAIT(1);        // K(s) landed
        __syncthreads();   // T visible; E consumed; K published
        if (s + 1 < 16) {
            load_e(s + 1);
            CP_COMMIT();
        }

        // ---- phase 2: QK^T (split precision) ----
        float sac[4][4] = {};
        #pragma unroll
        for (int kk = 0; kk < 64; kk += 16) {
            uint32_t ah4[4], al4[4];
            ldsm_x4(ah4, sb + SQH + ((wm * 16 + a_row) * EPITCH + kk + a_kof) * 2);
            ldsm_x4(al4, sb + SQL + ((wm * 16 + a_row) * EPITCH + kk + a_kof) * 2);
            #pragma unroll
            for (int np = 0; np < 2; np++) {
                uint32_t bh4[4], bl4[4];
                int roff = ((wn * 32 + np * 16 + b_nof) * EPITCH + kk + b_kof) * 2;
                ldsm_x4(bh4, sb + SKH + roff);
                ldsm_x4(bl4, sb + SKL + roff);
                #pragma unroll
                for (int t2 = 0; t2 < 2; t2++) {
                    float* cc = sac[np * 2 + t2];
                    mma16816(cc, ah4, &bh4[t2 * 2]);
                    mma16816(cc, ah4, &bl4[t2 * 2]);
                    mma16816(cc, al4, &bh4[t2 * 2]);
                }
            }
        }

        // gather T, exp, split P
        #pragma unroll
        for (int nt = 0; nt < 4; nt++) {
            int j = wn * 32 + nt * 8 + t * 2;
            float w0 = *(const float*)(smc + SW + (r0 + j) * 4);
            float w1 = *(const float*)(smc + SW + (r0 + j + 1) * 4);
            int jj0 = i0 - j + 63;
            int jj1 = i1 - j + 63;
            float t00 = __bfloat162float(*(const __nv_bfloat16*)(smc + ST + (i0 * TP + jj0) * 2));
            float t01 = __bfloat162float(*(const __nv_bfloat16*)(smc + ST + (i0 * TP + jj0 - 1) * 2));
            float t10 = __bfloat162float(*(const __nv_bfloat16*)(smc + ST + (i1 * TP + jj1) * 2));
            float t11 = __bfloat162float(*(const __nv_bfloat16*)(smc + ST + (i1 * TP + jj1 - 1) * 2));
            float p0 = __expf((sac[nt][0] + t00) * 0.125f) * w0;
            float p1 = __expf((sac[nt][1] + t01) * 0.125f) * w1;
            float p2 = __expf((sac[nt][2] + t10) * 0.125f) * w0;
            float p3 = __expf((sac[nt][3] + t11) * 0.125f) * w1;
            rs0 += p0 + p1;
            rs1 += p2 + p3;
            __nv_bfloat162 ph0, pl0, ph1, pl1;
            split_bf16(p0, ph0.x, pl0.x);
            split_bf16(p1, ph0.y, pl0.y);
            split_bf16(p2, ph1.x, pl1.x);
            split_bf16(p3, ph1.y, pl1.y);
            *(__nv_bfloat162*)(smc + SPH + (i0 * EPITCH + j) * 2) = ph0;
            *(__nv_bfloat162*)(smc + SPL + (i0 * EPITCH + j) * 2) = pl0;
            *(__nv_bfloat162*)(smc + SPH + (i1 * EPITCH + j) * 2) = ph1;
            *(__nv_bfloat162*)(smc + SPL + (i1 * EPITCH + j) * 2) = pl1;
        }
        if (s + 1 < 16) { CP_WAIT(1); } else { CP_WAIT(0); }   // V(s) landed
        __syncthreads();   // P visible; K consumed; V published
        if (s + 1 < 16) {
            load_k(s + 1);
            CP_COMMIT();
        }

        // ---- phase 3: PV (split precision) ----
        #pragma unroll
        for (int kk = 0; kk < 64; kk += 16) {
            uint32_t ph4[4], pl4[4];
            ldsm_x4(ph4, sb + SPH + ((wm * 16 + a_row) * EPITCH + kk + a_kof) * 2);
            ldsm_x4(pl4, sb + SPL + ((wm * 16 + a_row) * EPITCH + kk + a_kof) * 2);
            #pragma unroll
            for (int np = 0; np < 2; np++) {
                uint32_t bh4[4], bl4[4];
                int roff = ((wn * 32 + np * 16 + b_nof) * EPITCH + kk + b_kof) * 2;
                ldsm_x4(bh4, sb + SVH + roff);
                ldsm_x4(bl4, sb + SVL + roff);
                #pragma unroll
                for (int t2 = 0; t2 < 2; t2++) {
                    float* cc = oacc[np * 2 + t2];
                    mma16816(cc, ph4, &bh4[t2 * 2]);
                    mma16816(cc, ph4, &bl4[t2 * 2]);
                    mma16816(cc, pl4, &bh4[t2 * 2]);
                }
            }
        }
        if (s + 1 < 16) {
            CP_WAIT(1);        // E(s+1) landed
            __syncthreads();   // V/P consumed; E published
            load_v(s + 1);
            CP_COMMIT();
        } else {
            __syncthreads();   // before red-buffer reuse of ST
        }
    }

    // ---- finalize ----
    rs0 += __shfl_xor_sync(0xFFFFFFFFu, rs0, 1);
    rs0 += __shfl_xor_sync(0xFFFFFFFFu, rs0, 2);
    rs1 += __shfl_xor_sync(0xFFFFFFFFu, rs1, 1);
    rs1 += __shfl_xor_sync(0xFFFFFFFFu, rs1, 2);

    float* red = (float*)(smc + ST);
    red[i0 * 2 + wn] = rs0;
    red[i1 * 2 + wn] = rs1;
    __syncthreads();
    float inv0 = 1.0f / (1e-8f + red[i0 * 2] + red[i0 * 2 + 1]);
    float inv1 = 1.0f / (1e-8f + red[i1 * 2] + red[i1 * 2 + 1]);

    #pragma unroll
    for (int nt = 0; nt < 4; nt++) {
        int d = wn * 32 + nt * 8 + t * 2;
        float2 o0, o1;
        o0.x = oacc[nt][0] * inv0;
        o0.y = oacc[nt][1] * inv0;
        o1.x = oacc[nt][2] * inv1;
        o1.y = oacc[nt][3] * inv1;
        *(float2*)&out[(size_t)(b * SS + l0 + i0) * HIDD + h * 64 + d] = o0;
        *(float2*)&out[(size_t)(b * SS + l0 + i1) * HIDD + h * 64 + d] = o1;
    }
}

extern "C" void kernel_launch(void* const* d_in, const int* in_sizes, int n_in,
                              void* d_out, int out_size)
{
    const float* hs    = (const float*)d_in[0];
    const float* amask = (const float*)d_in[1];
    const int*   skm   = (const int*)  d_in[2];
    const float* Wq    = (const float*)d_in[3];
    const float* bq    = (const float*)d_in[4];
    const float* Wk    = (const float*)d_in[5];
    const float* bk    = (const float*)d_in[6];
    const float* Wv    = (const float*)d_in[7];
    const float* bv    = (const float*)d_in[8];
    const float* E     = (const float*)d_in[9];
    float* out = (float*)d_out;

    cudaFuncSetAttribute(qkv_tc_kernel, cudaFuncAttributeMaxDynamicSharedMemorySize, QSM_BYTES);
    cudaFuncSetAttribute(attn_tc_kernel, cudaFuncAttributeMaxDynamicSharedMemorySize, ASM_BYTES);

    conv_a_kernel<<<4096, 256>>>(hs);
    conv_w_kernel<<<dim3(32, 32, 3), dim3(32, 8)>>>(Wq, Wk, Wv);
    conv_e_kernel<<<128, 256>>>(E);
    conv_mask_kernel<<<16, 256>>>(amask, skm);
    qkv_tc_kernel<<<dim3(32, 24), 256, QSM_BYTES>>>(bq, bk, bv);
    conv_splitv_kernel<<<dim3(64, 16), 256>>>();
    attn_tc_kernel<<<dim3(16, 16, 4), 256, ASM_BYTES>>>(out);
}

// round 11
// speedup vs baseline: 4.4554x; 1.0360x over previous
#include <cuda_runtime.h>
#include <cuda_bf16.h>
#include <cstdint>
#include <cstddef>

#define BB 4
#define SS 1024
#define HIDD 1024
#define HH 16
#define DD 64

// pre-converted bf16 split operands for qkv GEMM
__device__ __nv_bfloat16 gAh[4096 * 1024];
__device__ __nv_bfloat16 gAl[4096 * 1024];
__device__ __nv_bfloat16 gBh[3 * 1024 * 1024];   // [sel][n][k]
__device__ __nv_bfloat16 gBl[3 * 1024 * 1024];

// bf16 split q/k/v for attention
__device__ __nv_bfloat16 gQh[BB*HH*SS*DD];
__device__ __nv_bfloat16 gQl[BB*HH*SS*DD];
__device__ __nv_bfloat16 gKh[BB*HH*SS*DD];
__device__ __nv_bfloat16 gKl[BB*HH*SS*DD];
__device__ __nv_bfloat16 gVth[BB*HH*DD*SS];      // [bh][d][s] transposed
__device__ __nv_bfloat16 gVtl[BB*HH*DD*SS];
__device__ __nv_bfloat16 gEh[2047 * 64];         // dist_emb bf16 (hi)
__device__ float gWcomb[BB * SS];                // exp(amask)*skim

__device__ __forceinline__ uint32_t smem_u32(const void* p) {
    uint32_t a;
    asm("{ .reg .u64 t; cvta.to.shared.u64 t, %1; cvt.u32.u64 %0, t; }" : "=r"(a) : "l"(p));
    return a;
}
__device__ __forceinline__ void ldsm_x4(uint32_t* r, uint32_t addr) {
    asm volatile("ldmatrix.sync.aligned.m8n8.x4.shared.b16 {%0,%1,%2,%3}, [%4];"
        : "=r"(r[0]), "=r"(r[1]), "=r"(r[2]), "=r"(r[3]) : "r"(addr));
}
__device__ __forceinline__ void mma16816(float* c, const uint32_t* a, const uint32_t* b) {
    asm volatile(
        "mma.sync.aligned.m16n8k16.row.col.f32.bf16.bf16.f32 "
        "{%0,%1,%2,%3}, {%4,%5,%6,%7}, {%8,%9}, {%0,%1,%2,%3};"
        : "+f"(c[0]), "+f"(c[1]), "+f"(c[2]), "+f"(c[3])
        : "r"(a[0]), "r"(a[1]), "r"(a[2]), "r"(a[3]), "r"(b[0]), "r"(b[1]));
}
__device__ __forceinline__ void cp16(uint32_t dst, const void* src) {
    asm volatile("cp.async.cg.shared.global [%0], [%1], 16;" :: "r"(dst), "l"(src));
}
#define CP_COMMIT() asm volatile("cp.async.commit_group;" ::: "memory")
#define CP_WAIT(N)  asm volatile("cp.async.wait_group %0;" :: "n"(N) : "memory")

__device__ __forceinline__ void split_bf16(float v, __nv_bfloat16& h, __nv_bfloat16& l) {
    h = __float2bfloat16_rn(v);
    l = __float2bfloat16_rn(v - __bfloat162float(h));
}

// ---------------------------------------------------------------------------
// conv_all: fused A-split / W-transpose-split / E / mask preconversion.
// grid: [0,4096) A, [4096,7168) W, [7168,7296) E, [7296,7312) mask.
// ---------------------------------------------------------------------------
__global__ __launch_bounds__(256) void conv_all_kernel(
    const float* __restrict__ A,
    const float* __restrict__ Wq, const float* __restrict__ Wk, const float* __restrict__ Wv,
    const float* __restrict__ E,
    const float* __restrict__ am, const int* __restrict__ sk)
{
    __shared__ float t[32][33];
    int bid = blockIdx.x;
    int tid = threadIdx.x;

    if (bid < 4096) {
        int idx = bid * 256 + tid;
        float4 a4 = *(const float4*)&A[(size_t)idx * 4];
        __nv_bfloat16 h[4], l[4];
        split_bf16(a4.x, h[0], l[0]);
        split_bf16(a4.y, h[1], l[1]);
        split_bf16(a4.z, h[2], l[2]);
        split_bf16(a4.w, h[3], l[3]);
        *(uint2*)&gAh[(size_t)idx * 4] = *(uint2*)h;
        *(uint2*)&gAl[(size_t)idx * 4] = *(uint2*)l;
    } else if (bid < 7168) {
        int id = bid - 4096;
        int sel = id >> 10;
        int rem = id & 1023;
        int n0 = (rem & 31) * 32, k0 = (rem >> 5) * 32;
        const float* W = (sel == 0) ? Wq : (sel == 1) ? Wk : Wv;
        int tx = tid & 31, ty = tid >> 5;

        #pragma unroll
        for (int r = ty; r < 32; r += 8)
            t[r][tx] = W[(size_t)(k0 + r) * HIDD + n0 + tx];
        __syncthreads();
        size_t base = (size_t)sel * 1024 * 1024;
        #pragma unroll
        for (int r = ty; r < 32; r += 8) {
            float v = t[tx][r];
            __nv_bfloat16 h, l;
            split_bf16(v, h, l);
            gBh[base + (size_t)(n0 + r) * 1024 + k0 + tx] = h;
            gBl[base + (size_t)(n0 + r) * 1024 + k0 + tx] = l;
        }
    } else if (bid < 7296) {
        int i4 = (bid - 7168) * 256 + tid;
        if (i4 < 2047 * 16) {
            float4 a4 = *(const float4*)&E[(size_t)i4 * 4];
            __nv_bfloat16 h[4];
            h[0] = __float2bfloat16_rn(a4.x);
            h[1] = __float2bfloat16_rn(a4.y);
            h[2] = __float2bfloat16_rn(a4.z);
            h[3] = __float2bfloat16_rn(a4.w);
            *(uint2*)&gEh[(size_t)i4 * 4] = *(uint2*)h;
        }
    } else {
        int i = (bid - 7296) * 256 + tid;
        gWcomb[i] = __expf(am[i]) * (float)sk[i];
    }
}

// ---------------------------------------------------------------------------
// QKV GEMM: mainloop proven. Epilogue: Q/K split bf16 direct; V transposed
// in smem (buffers dead after mainloop) and written split to gVth/gVtl.
// ---------------------------------------------------------------------------
#define APITCH 40
#define TILE_B (128 * APITCH * 2)
#define STAGE_B (4 * TILE_B)
#define QSM_BYTES (2 * STAGE_B)
#define VSP 136      // V-stage pitch (bf16 elems); row = 272 B (16-aligned)

__global__ __launch_bounds__(256, 2) void qkv_tc_kernel(
    const float* __restrict__ bq, const float* __restrict__ bk, const float* __restrict__ bv)
{
    extern __shared__ char smc[];
    uint32_t sb = smem_u32(smc);

    int tid  = threadIdx.x;
    int wid  = tid >> 5;
    int lane = tid & 31;
    int wm = wid & 3;
    int wn = wid >> 2;

    int m0  = blockIdx.x * 128;
    int ng0 = blockIdx.y * 128;
    int sel = ng0 >> 10;
    int n0  = ng0 & 1023;

    const float* bias = (sel == 0) ? bq : (sel == 1) ? bk : bv;

    const __nv_bfloat16* pAh = gAh + (size_t)m0 * 1024;
    const __nv_bfloat16* pAl = gAl + (size_t)m0 * 1024;
    const __nv_bfloat16* pBh = gBh + (size_t)sel * 1048576 + (size_t)n0 * 1024;
    const __nv_bfloat16* pBl = gBl + (size_t)sel * 1048576 + (size_t)n0 * 1024;

    auto copy_stage = [&](int s, int buf) {
        int k0 = s * 32;
        uint32_t bbase = sb + buf * STAGE_B;
        #pragma unroll
        for (int p = 0; p < 8; p++) {
            int tile = p >> 1;
            int cidx = tid + (p & 1) * 256;
            int row = cidx >> 2, ch = cidx & 3;
            const __nv_bfloat16* src =
                (tile == 0) ? pAh : (tile == 1) ? pAl : (tile == 2) ? pBh : pBl;
            cp16(bbase + tile * TILE_B + row * (APITCH * 2) + ch * 16,
                 src + (size_t)row * 1024 + k0 + ch * 8);
        }
        CP_COMMIT();
    };

    float acc[2][8][4] = {};

    int a_row = (lane & 15);
    int a_kof = (lane >> 4) * 8;
    int b_nof = (lane & 7) | ((lane >> 4) << 3);
    int b_kof = ((lane >> 3) & 1) * 8;

    copy_stage(0, 0);

    for (int s = 0; s < 32; s++) {
        int buf = s & 1;
        if (s + 1 < 32) {
            copy_stage(s + 1, buf ^ 1);
            CP_WAIT(1);
        } else {
            CP_WAIT(0);
        }
        __syncthreads();

        uint32_t bAh = sb + buf * STAGE_B;
        uint32_t bAl = bAh + TILE_B;
        uint32_t bBh = bAl + TILE_B;
        uint32_t bBl = bBh + TILE_B;

        #pragma unroll
        for (int kk = 0; kk < 32; kk += 16) {
            uint32_t ah[2][4], al[2][4];
            #pragma unroll
            for (int mt = 0; mt < 2; mt++) {
                int off = ((wm * 32 + mt * 16 + a_row) * APITCH + kk + a_kof) * 2;
                ldsm_x4(ah[mt], bAh + off);
                ldsm_x4(al[mt], bAl + off);
            }
            #pragma unroll
            for (int np = 0; np < 4; np++) {
                uint32_t bh4[4], bl4[4];
                int off = ((wn * 64 + np * 16 + b_nof) * APITCH + kk + b_kof) * 2;
                ldsm_x4(bh4, bBh + off);
                ldsm_x4(bl4, bBl + off);
                #pragma unroll
                for (int mt = 0; mt < 2; mt++)
                    #pragma unroll
                    for (int t = 0; t < 2; t++) {
                        float* c = acc[mt][np * 2 + t];
                        mma16816(c, ah[mt], &bh4[t * 2]);
                        mma16816(c, ah[mt], &bl4[t * 2]);
                        mma16816(c, al[mt], &bh4[t * 2]);
                    }
            }
        }
        __syncthreads();
    }

    int g = lane >> 2, t = lane & 3;

    if (sel != 2) {
        // Q/K: split bf16 direct to [B,H,S,D]
        #pragma unroll
        for (int nt = 0; nt < 8; nt++) {
            int nc = n0 + wn * 64 + nt * 8 + t * 2;
            int h_ = nc >> 6, d = nc & 63;
            float b0 = bias[nc], b1 = bias[nc + 1];
            #pragma unroll
            for (int mt = 0; mt < 2; mt++) {
                #pragma unroll
                for (int half = 0; half < 2; half++) {
                    int m = m0 + wm * 32 + mt * 16 + g + half * 8;
                    int b_ = m >> 10, s_ = m & 1023;
                    float vx = acc[mt][nt][half * 2 + 0] + b0;
                    float vy = acc[mt][nt][half * 2 + 1] + b1;
                    size_t off = ((size_t)(b_ * HH + h_) * SS + s_) * DD + d;
                    __nv_bfloat162 oh, ol;
                    split_bf16(vx, oh.x, ol.x);
                    split_bf16(vy, oh.y, ol.y);
                    if (sel == 0) {
                        *(__nv_bfloat162*)&gQh[off] = oh;
                        *(__nv_bfloat162*)&gQl[off] = ol;
                    } else {
                        *(__nv_bfloat162*)&gKh[off] = oh;
                        *(__nv_bfloat162*)&gKl[off] = ol;
                    }
                }
            }
        }
    } else {
        // V: transpose in smem (mainloop buffers are dead), write [bh][d][s]
        __nv_bfloat16* stgh = (__nv_bfloat16*)smc;           // [128][VSP]
        __nv_bfloat16* stgl = stgh + 128 * VSP;
        #pragma unroll
        for (int nt = 0; nt < 8; nt++) {
            int ncl = wn * 64 + nt * 8 + t * 2;
            int nc = n0 + ncl;
            float b0 = bias[nc], b1 = bias[nc + 1];
            #pragma unroll
            for (int mt = 0; mt < 2; mt++) {
                #pragma unroll
                for (int half = 0; half < 2; half++) {
                    int ml = wm * 32 + mt * 16 + g + half * 8;
                    float vx = acc[mt][nt][half * 2 + 0] + b0;
                    float vy = acc[mt][nt][half * 2 + 1] + b1;
                    __nv_bfloat16 hx, lx, hy, ly;
                    split_bf16(vx, hx, lx);
                    split_bf16(vy, hy, ly);
                    stgh[ncl * VSP + ml] = hx;
                    stgh[(ncl + 1) * VSP + ml] = hy;
                    stgl[ncl * VSP + ml] = lx;
                    stgl[(ncl + 1) * VSP + ml] = ly;
                }
            }
        }
        __syncthreads();
        int b_ = m0 >> 10, sm0 = m0 & 1023;
        #pragma unroll
        for (int p = 0; p < 8; p++) {
            int idx = tid + p * 256;
            int row = idx >> 4;        // nc_local 0..127
            int ch = idx & 15;         // 8-elem (16 B) chunk
            int nc = n0 + row;
            int h_ = nc >> 6, d = nc & 63;
            size_t go = ((size_t)(b_ * HH + h_) * DD + d) * SS + sm0 + ch * 8;
            *(uint4*)&gVth[go] = *(uint4*)&stgh[row * VSP + ch * 8];
            *(uint4*)&gVtl[go] = *(uint4*)&stgl[row * VSP + ch * 8];
        }
    }
}

// ---------------------------------------------------------------------------
// attn_tc (unchanged, proven): 64-query CTA, 2 CTAs/SM, staggered E/K/V
// cp.async groups, 3 syncs/tile. grid (16, 16, 4).
// ---------------------------------------------------------------------------
#define EPITCH 72
#define ROWB 144
#define TP 136
#define SQH 0
#define SQL 9216
#define SKH 18432
#define SKL 27648
#define SVH 36864
#define SVL 46080
#define SE  55296
#define ST  73728
#define SPH 91136
#define SPL 100352
#define SW  109568
#define ASM_BYTES 113664

__global__ __launch_bounds__(256, 2) void attn_tc_kernel(float* __restrict__ out)
{
    extern __shared__ char smc[];
    uint32_t sb = smem_u32(smc);
    int tid = threadIdx.x, wid = tid >> 5, lane = tid & 31;
    int wm = wid & 3, wn = wid >> 2;
    int b = blockIdx.z, h = blockIdx.y;
    int l0 = blockIdx.x * 64;
    int bh = b * HH + h;

    const __nv_bfloat16* pQh = gQh + ((size_t)bh * SS + l0) * DD;
    const __nv_bfloat16* pQl = gQl + ((size_t)bh * SS + l0) * DD;
    const __nv_bfloat16* pKh = gKh + (size_t)bh * SS * DD;
    const __nv_bfloat16* pKl = gKl + (size_t)bh * SS * DD;
    const __nv_bfloat16* pVh = gVth + (size_t)bh * DD * SS;
    const __nv_bfloat16* pVl = gVtl + (size_t)bh * DD * SS;

    int a_row = lane & 15;
    int a_kof = (lane >> 4) * 8;
    int b_nof = (lane & 7) | ((lane >> 4) << 3);
    int b_kof = ((lane >> 3) & 1) * 8;
    int g = lane >> 2, t = lane & 3;

    auto load_k = [&](int s2) {
        int rr = s2 * 64;
        #pragma unroll
        for (int p = 0; p < 4; p++) {
            int idx = tid + p * 256;
            int arr = idx >> 9, rc = idx & 511;
            int row = rc >> 3, ch = rc & 7;
            const __nv_bfloat16* src = (arr == 0)
                ? pKh + (size_t)(rr + row) * 64 + ch * 8
                : pKl + (size_t)(rr + row) * 64 + ch * 8;
            cp16(sb + SKH + arr * 9216 + row * ROWB + ch * 16, src);
        }
    };
    auto load_v = [&](int s2) {
        int rr = s2 * 64;
        #pragma unroll
        for (int p = 0; p < 4; p++) {
            int idx = tid + p * 256;
            int arr = idx >> 9, rc = idx & 511;
            int row = rc >> 3, ch = rc & 7;
            const __nv_bfloat16* src = (arr == 0)
                ? pVh + (size_t)row * SS + rr + ch * 8
                : pVl + (size_t)row * SS + rr + ch * 8;
            cp16(sb + SVH + arr * 9216 + row * ROWB + ch * 16, src);
        }
    };
    auto load_e = [&](int s2) {
        int base = l0 - s2 * 64 + 960;
        #pragma unroll
        for (int p = 0; p < 4; p++) {
            int idx = tid + p * 256;
            int row = idx >> 3, ch = idx & 7;
            int er = base + row;
            if (er > 2046) er = 2046;
            cp16(sb + SE + row * ROWB + ch * 16, gEh + (size_t)er * 64 + ch * 8);
        }
    };

    #pragma unroll
    for (int p = 0; p < 4; p++) {
        int idx = tid + p * 256;
        int arr = idx >> 9, rc = idx & 511;
        int row = rc >> 3, ch = rc & 7;
        cp16(sb + (arr ? SQL : SQH) + row * ROWB + ch * 16,
             (arr ? pQl : pQh) + (size_t)row * 64 + ch * 8);
    }
    cp16(sb + SW + tid * 16, gWcomb + b * SS + tid * 4);
    load_e(0);
    CP_COMMIT();
    load_k(0);
    CP_COMMIT();
    load_v(0);
    CP_COMMIT();

    CP_WAIT(2);
    __syncthreads();

    float oacc[4][4] = {};
    float rs0 = 0.f, rs1 = 0.f;
    int i0 = wm * 16 + g, i1 = i0 + 8;

    for (int s = 0; s < 16; s++) {
        int r0 = s * 64;

        // ---- phase 1: bias GEMM T[64x128] = Qh @ E_band^T ----
        {
            float tac[8][4] = {};
            #pragma unroll
            for (int kk = 0; kk < 64; kk += 16) {
                uint32_t ah4[4];
                ldsm_x4(ah4, sb + SQH + ((wm * 16 + a_row) * EPITCH + kk + a_kof) * 2);
                #pragma unroll
                for (int np = 0; np < 4; np++) {
                    uint32_t eb4[4];
                    ldsm_x4(eb4, sb + SE + ((wn * 64 + np * 16 + b_nof) * EPITCH + kk + b_kof) * 2);
                    mma16816(tac[np * 2 + 0], ah4, &eb4[0]);
                    mma16816(tac[np * 2 + 1], ah4, &eb4[2]);
                }
            }
            #pragma unroll
            for (int nt = 0; nt < 8; nt++) {
                int col = wn * 64 + nt * 8 + t * 2;
                __nv_bfloat162 v0, v1;
                v0.x = __float2bfloat16_rn(tac[nt][0]);
                v0.y = __float2bfloat16_rn(tac[nt][1]);
                v1.x = __float2bfloat16_rn(tac[nt][2]);
                v1.y = __float2bfloat16_rn(tac[nt][3]);
                *(__nv_bfloat162*)(smc + ST + (i0 * TP + col) * 2) = v0;
                *(__nv_bfloat162*)(smc + ST + (i1 * TP + col) * 2) = v1;
            }
        }
        CP_WAIT(1);
        __syncthreads();
        if (s + 1 < 16) {
            load_e(s + 1);
            CP_COMMIT();
        }

        // ---- phase 2: QK^T (split precision) ----
        float sac[4][4] = {};
        #pragma unroll
        for (int kk = 0; kk < 64; kk += 16) {
            uint32_t ah4[4], al4[4];
            ldsm_x4(ah4, sb + SQH + ((wm * 16 + a_row) * EPITCH + kk + a_kof) * 2);
            ldsm_x4(al4, sb + SQL + ((wm * 16 + a_row) * EPITCH + kk + a_kof) * 2);
            #pragma unroll
            for (int np = 0; np < 2; np++) {
                uint32_t bh4[4], bl4[4];
                int roff = ((wn * 32 + np * 16 + b_nof) * EPITCH + kk + b_kof) * 2;
                ldsm_x4(bh4, sb + SKH + roff);
                ldsm_x4(bl4, sb + SKL + roff);
                #pragma unroll
                for (int t2 = 0; t2 < 2; t2++) {
                    float* cc = sac[np * 2 + t2];
                    mma16816(cc, ah4, &bh4[t2 * 2]);
                    mma16816(cc, ah4, &bl4[t2 * 2]);
                    mma16816(cc, al4, &bh4[t2 * 2]);
                }
            }
        }

        #pragma unroll
        for (int nt = 0; nt < 4; nt++) {
            int j = wn * 32 + nt * 8 + t * 2;
            float w0 = *(const float*)(smc + SW + (r0 + j) * 4);
            float w1 = *(const float*)(smc + SW + (r0 + j + 1) * 4);
            int jj0 = i0 - j + 63;
            int jj1 = i1 - j + 63;
            float t00 = __bfloat162float(*(const __nv_bfloat16*)(smc + ST + (i0 * TP + jj0) * 2));
            float t01 = __bfloat162float(*(const __nv_bfloat16*)(smc + ST + (i0 * TP + jj0 - 1) * 2));
            float t10 = __bfloat162float(*(const __nv_bfloat16*)(smc + ST + (i1 * TP + jj1) * 2));
            float t11 = __bfloat162float(*(const __nv_bfloat16*)(smc + ST + (i1 * TP + jj1 - 1) * 2));
            float p0 = __expf((sac[nt][0] + t00) * 0.125f) * w0;
            float p1 = __expf((sac[nt][1] + t01) * 0.125f) * w1;
            float p2 = __expf((sac[nt][2] + t10) * 0.125f) * w0;
            float p3 = __expf((sac[nt][3] + t11) * 0.125f) * w1;
            rs0 += p0 + p1;
            rs1 += p2 + p3;
            __nv_bfloat162 ph0, pl0, ph1, pl1;
            split_bf16(p0, ph0.x, pl0.x);
            split_bf16(p1, ph0.y, pl0.y);
            split_bf16(p2, ph1.x, pl1.x);
            split_bf16(p3, ph1.y, pl1.y);
            *(__nv_bfloat162*)(smc + SPH + (i0 * EPITCH + j) * 2) = ph0;
            *(__nv_bfloat162*)(smc + SPL + (i0 * EPITCH + j) * 2) = pl0;
            *(__nv_bfloat162*)(smc + SPH + (i1 * EPITCH + j) * 2) = ph1;
            *(__nv_bfloat162*)(smc + SPL + (i1 * EPITCH + j) * 2) = pl1;
        }
        if (s + 1 < 16) { CP_WAIT(1); } else { CP_WAIT(0); }
        __syncthreads();
        if (s + 1 < 16) {
            load_k(s + 1);
            CP_COMMIT();
        }

        // ---- phase 3: PV (split precision) ----
        #pragma unroll
        for (int kk = 0; kk < 64; kk += 16) {
            uint32_t ph4[4], pl4[4];
            ldsm_x4(ph4, sb + SPH + ((wm * 16 + a_row) * EPITCH + kk + a_kof) * 2);
            ldsm_x4(pl4, sb + SPL + ((wm * 16 + a_row) * EPITCH + kk + a_kof) * 2);
            #pragma unroll
            for (int np = 0; np < 2; np++) {
                uint32_t bh4[4], bl4[4];
                int roff = ((wn * 32 + np * 16 + b_nof) * EPITCH + kk + b_kof) * 2;
                ldsm_x4(bh4, sb + SVH + roff);
                ldsm_x4(bl4, sb + SVL + roff);
                #pragma unroll
                for (int t2 = 0; t2 < 2; t2++) {
                    float* cc = oacc[np * 2 + t2];
                    mma16816(cc, ph4, &bh4[t2 * 2]);
                    mma16816(cc, ph4, &bl4[t2 * 2]);
                    mma16816(cc, pl4, &bh4[t2 * 2]);
                }
            }
        }
        if (s + 1 < 16) {
            CP_WAIT(1);
            __syncthreads();
            load_v(s + 1);
            CP_COMMIT();
        } else {
            __syncthreads();
        }
    }

    // ---- finalize ----
    rs0 += __shfl_xor_sync(0xFFFFFFFFu, rs0, 1);
    rs0 += __shfl_xor_sync(0xFFFFFFFFu, rs0, 2);
    rs1 += __shfl_xor_sync(0xFFFFFFFFu, rs1, 1);
    rs1 += __shfl_xor_sync(0xFFFFFFFFu, rs1, 2);

    float* red = (float*)(smc + ST);
    red[i0 * 2 + wn] = rs0;
    red[i1 * 2 + wn] = rs1;
    __syncthreads();
    float inv0 = 1.0f / (1e-8f + red[i0 * 2] + red[i0 * 2 + 1]);
    float inv1 = 1.0f / (1e-8f + red[i1 * 2] + red[i1 * 2 + 1]);

    #pragma unroll
    for (int nt = 0; nt < 4; nt++) {
        int d = wn * 32 + nt * 8 + t * 2;
        float2 o0, o1;
        o0.x = oacc[nt][0] * inv0;
        o0.y = oacc[nt][1] * inv0;
        o1.x = oacc[nt][2] * inv1;
        o1.y = oacc[nt][3] * inv1;
        *(float2*)&out[(size_t)(b * SS + l0 + i0) * HIDD + h * 64 + d] = o0;
        *(float2*)&out[(size_t)(b * SS + l0 + i1) * HIDD + h * 64 + d] = o1;
    }
}

extern "C" void kernel_launch(void* const* d_in, const int* in_sizes, int n_in,
                              void* d_out, int out_size)
{
    const float* hs    = (const float*)d_in[0];
    const float* amask = (const float*)d_in[1];
    const int*   skm   = (const int*)  d_in[2];
    const float* Wq    = (const float*)d_in[3];
    const float* bq    = (const float*)d_in[4];
    const float* Wk    = (const float*)d_in[5];
    const float* bk    = (const float*)d_in[6];
    const float* Wv    = (const float*)d_in[7];
    const float* bv    = (const float*)d_in[8];
    const float* E     = (const float*)d_in[9];
    float* out = (float*)d_out;

    cudaFuncSetAttribute(qkv_tc_kernel, cudaFuncAttributeMaxDynamicSharedMemorySize, QSM_BYTES);
    cudaFuncSetAttribute(attn_tc_kernel, cudaFuncAttributeMaxDynamicSharedMemorySize, ASM_BYTES);

    conv_all_kernel<<<7312, 256>>>(hs, Wq, Wk, Wv, E, amask, skm);
    qkv_tc_kernel<<<dim3(32, 24), 256, QSM_BYTES>>>(bq, bk, bv);
    attn_tc_kernel<<<dim3(16, 16, 4), 256, ASM_BYTES>>>(out);
}

// round 15
// speedup vs baseline: 4.5881x; 1.0298x over previous
#include <cuda_runtime.h>
#include <cuda_bf16.h>
#include <cstdint>
#include <cstddef>

#define BB 4
#define SS 1024
#define HIDD 1024
#define HH 16
#define DD 64

// pre-converted bf16 split operands for qkv GEMM
__device__ __nv_bfloat16 gAh[4096 * 1024];
__device__ __nv_bfloat16 gAl[4096 * 1024];
__device__ __nv_bfloat16 gBh[3 * 1024 * 1024];   // [sel][n][k]
__device__ __nv_bfloat16 gBl[3 * 1024 * 1024];

// bf16 split q/k/v for attention
__device__ __nv_bfloat16 gQh[BB*HH*SS*DD];
__device__ __nv_bfloat16 gQl[BB*HH*SS*DD];
__device__ __nv_bfloat16 gKh[BB*HH*SS*DD];
__device__ __nv_bfloat16 gKl[BB*HH*SS*DD];
__device__ __nv_bfloat16 gVth[BB*HH*DD*SS];      // [bh][d][s] transposed
__device__ __nv_bfloat16 gVtl[BB*HH*DD*SS];
__device__ __nv_bfloat16 gEh[2047 * 64];         // dist_emb bf16 (hi)
__device__ float gWcomb[BB * SS];                // exp(amask)*skim

__device__ __forceinline__ uint32_t smem_u32(const void* p) {
    uint32_t a;
    asm("{ .reg .u64 t; cvta.to.shared.u64 t, %1; cvt.u32.u64 %0, t; }" : "=r"(a) : "l"(p));
    return a;
}
__device__ __forceinline__ void ldsm_x4(uint32_t* r, uint32_t addr) {
    asm volatile("ldmatrix.sync.aligned.m8n8.x4.shared.b16 {%0,%1,%2,%3}, [%4];"
        : "=r"(r[0]), "=r"(r[1]), "=r"(r[2]), "=r"(r[3]) : "r"(addr));
}
__device__ __forceinline__ void mma16816(float* c, const uint32_t* a, const uint32_t* b) {
    asm volatile(
        "mma.sync.aligned.m16n8k16.row.col.f32.bf16.bf16.f32 "
        "{%0,%1,%2,%3}, {%4,%5,%6,%7}, {%8,%9}, {%0,%1,%2,%3};"
        : "+f"(c[0]), "+f"(c[1]), "+f"(c[2]), "+f"(c[3])
        : "r"(a[0]), "r"(a[1]), "r"(a[2]), "r"(a[3]), "r"(b[0]), "r"(b[1]));
}
__device__ __forceinline__ void cp16(uint32_t dst, const void* src) {
    asm volatile("cp.async.cg.shared.global [%0], [%1], 16;" :: "r"(dst), "l"(src));
}
#define CP_COMMIT() asm volatile("cp.async.commit_group;" ::: "memory")
#define CP_WAIT(N)  asm volatile("cp.async.wait_group %0;" :: "n"(N) : "memory")

__device__ __forceinline__ void split_bf16(float v, __nv_bfloat16& h, __nv_bfloat16& l) {
    h = __float2bfloat16_rn(v);
    l = __float2bfloat16_rn(v - __bfloat162float(h));
}
__device__ __forceinline__ uint32_t pack_bf16x2(float lo, float hi) {
    uint32_t r;
    asm("cvt.rn.bf16x2.f32 %0, %1, %2;" : "=r"(r) : "f"(hi), "f"(lo));
    return r;
}

// ---------------------------------------------------------------------------
// conv_all: fused A-split / W-transpose-split / E / mask preconversion.
// grid: [0,4096) A, [4096,7168) W, [7168,7296) E, [7296,7312) mask.
// ---------------------------------------------------------------------------
__global__ __launch_bounds__(256) void conv_all_kernel(
    const float* __restrict__ A,
    const float* __restrict__ Wq, const float* __restrict__ Wk, const float* __restrict__ Wv,
    const float* __restrict__ E,
    const float* __restrict__ am, const int* __restrict__ sk)
{
    __shared__ float t[32][33];
    int bid = blockIdx.x;
    int tid = threadIdx.x;

    if (bid < 4096) {
        int idx = bid * 256 + tid;
        float4 a4 = *(const float4*)&A[(size_t)idx * 4];
        __nv_bfloat16 h[4], l[4];
        split_bf16(a4.x, h[0], l[0]);
        split_bf16(a4.y, h[1], l[1]);
        split_bf16(a4.z, h[2], l[2]);
        split_bf16(a4.w, h[3], l[3]);
        *(uint2*)&gAh[(size_t)idx * 4] = *(uint2*)h;
        *(uint2*)&gAl[(size_t)idx * 4] = *(uint2*)l;
    } else if (bid < 7168) {
        int id = bid - 4096;
        int sel = id >> 10;
        int rem = id & 1023;
        int n0 = (rem & 31) * 32, k0 = (rem >> 5) * 32;
        const float* W = (sel == 0) ? Wq : (sel == 1) ? Wk : Wv;
        int tx = tid & 31, ty = tid >> 5;

        #pragma unroll
        for (int r = ty; r < 32; r += 8)
            t[r][tx] = W[(size_t)(k0 + r) * HIDD + n0 + tx];
        __syncthreads();
        size_t base = (size_t)sel * 1024 * 1024;
        #pragma unroll
        for (int r = ty; r < 32; r += 8) {
            float v = t[tx][r];
            __nv_bfloat16 h, l;
            split_bf16(v, h, l);
            gBh[base + (size_t)(n0 + r) * 1024 + k0 + tx] = h;
            gBl[base + (size_t)(n0 + r) * 1024 + k0 + tx] = l;
        }
    } else if (bid < 7296) {
        int i4 = (bid - 7168) * 256 + tid;
        if (i4 < 2047 * 16) {
            float4 a4 = *(const float4*)&E[(size_t)i4 * 4];
            __nv_bfloat16 h[4];
            h[0] = __float2bfloat16_rn(a4.x);
            h[1] = __float2bfloat16_rn(a4.y);
            h[2] = __float2bfloat16_rn(a4.z);
            h[3] = __float2bfloat16_rn(a4.w);
            *(uint2*)&gEh[(size_t)i4 * 4] = *(uint2*)h;
        }
    } else {
        int i = (bid - 7296) * 256 + tid;
        gWcomb[i] = __expf(am[i]) * (float)sk[i];
    }
}

// ---------------------------------------------------------------------------
// QKV GEMM (proven): Q/K split bf16 direct; V transposed in smem.
// ---------------------------------------------------------------------------
#define APITCH 40
#define TILE_B (128 * APITCH * 2)
#define STAGE_B (4 * TILE_B)
#define QSM_BYTES (2 * STAGE_B)
#define VSP 136

__global__ __launch_bounds__(256, 2) void qkv_tc_kernel(
    const float* __restrict__ bq, const float* __restrict__ bk, const float* __restrict__ bv)
{
    extern __shared__ char smc[];
    uint32_t sb = smem_u32(smc);

    int tid  = threadIdx.x;
    int wid  = tid >> 5;
    int lane = tid & 31;
    int wm = wid & 3;
    int wn = wid >> 2;

    int m0  = blockIdx.x * 128;
    int ng0 = blockIdx.y * 128;
    int sel = ng0 >> 10;
    int n0  = ng0 & 1023;

    const float* bias = (sel == 0) ? bq : (sel == 1) ? bk : bv;

    const __nv_bfloat16* pAh = gAh + (size_t)m0 * 1024;
    const __nv_bfloat16* pAl = gAl + (size_t)m0 * 1024;
    const __nv_bfloat16* pBh = gBh + (size_t)sel * 1048576 + (size_t)n0 * 1024;
    const __nv_bfloat16* pBl = gBl + (size_t)sel * 1048576 + (size_t)n0 * 1024;

    auto copy_stage = [&](int s, int buf) {
        int k0 = s * 32;
        uint32_t bbase = sb + buf * STAGE_B;
        #pragma unroll
        for (int p = 0; p < 8; p++) {
            int tile = p >> 1;
            int cidx = tid + (p & 1) * 256;
            int row = cidx >> 2, ch = cidx & 3;
            const __nv_bfloat16* src =
                (tile == 0) ? pAh : (tile == 1) ? pAl : (tile == 2) ? pBh : pBl;
            cp16(bbase + tile * TILE_B + row * (APITCH * 2) + ch * 16,
                 src + (size_t)row * 1024 + k0 + ch * 8);
        }
        CP_COMMIT();
    };

    float acc[2][8][4] = {};

    int a_row = (lane & 15);
    int a_kof = (lane >> 4) * 8;
    int b_nof = (lane & 7) | ((lane >> 4) << 3);
    int b_kof = ((lane >> 3) & 1) * 8;

    copy_stage(0, 0);

    for (int s = 0; s < 32; s++) {
        int buf = s & 1;
        if (s + 1 < 32) {
            copy_stage(s + 1, buf ^ 1);
            CP_WAIT(1);
        } else {
            CP_WAIT(0);
        }
        __syncthreads();

        uint32_t bAh = sb + buf * STAGE_B;
        uint32_t bAl = bAh + TILE_B;
        uint32_t bBh = bAl + TILE_B;
        uint32_t bBl = bBh + TILE_B;

        #pragma unroll
        for (int kk = 0; kk < 32; kk += 16) {
            uint32_t ah[2][4], al[2][4];
            #pragma unroll
            for (int mt = 0; mt < 2; mt++) {
                int off = ((wm * 32 + mt * 16 + a_row) * APITCH + kk + a_kof) * 2;
                ldsm_x4(ah[mt], bAh + off);
                ldsm_x4(al[mt], bAl + off);
            }
            #pragma unroll
            for (int np = 0; np < 4; np++) {
                uint32_t bh4[4], bl4[4];
                int off = ((wn * 64 + np * 16 + b_nof) * APITCH + kk + b_kof) * 2;
                ldsm_x4(bh4, bBh + off);
                ldsm_x4(bl4, bBl + off);
                #pragma unroll
                for (int mt = 0; mt < 2; mt++)
                    #pragma unroll
                    for (int t = 0; t < 2; t++) {
                        float* c = acc[mt][np * 2 + t];
                        mma16816(c, ah[mt], &bh4[t * 2]);
                        mma16816(c, ah[mt], &bl4[t * 2]);
                        mma16816(c, al[mt], &bh4[t * 2]);
                    }
            }
        }
        __syncthreads();
    }

    int g = lane >> 2, t = lane & 3;

    if (sel != 2) {
        #pragma unroll
        for (int nt = 0; nt < 8; nt++) {
            int nc = n0 + wn * 64 + nt * 8 + t * 2;
            int h_ = nc >> 6, d = nc & 63;
            float b0 = bias[nc], b1 = bias[nc + 1];
            #pragma unroll
            for (int mt = 0; mt < 2; mt++) {
                #pragma unroll
                for (int half = 0; half < 2; half++) {
                    int m = m0 + wm * 32 + mt * 16 + g + half * 8;
                    int b_ = m >> 10, s_ = m & 1023;
                    float vx = acc[mt][nt][half * 2 + 0] + b0;
                    float vy = acc[mt][nt][half * 2 + 1] + b1;
                    size_t off = ((size_t)(b_ * HH + h_) * SS + s_) * DD + d;
                    __nv_bfloat162 oh, ol;
                    split_bf16(vx, oh.x, ol.x);
                    split_bf16(vy, oh.y, ol.y);
                    if (sel == 0) {
                        *(__nv_bfloat162*)&gQh[off] = oh;
                        *(__nv_bfloat162*)&gQl[off] = ol;
                    } else {
                        *(__nv_bfloat162*)&gKh[off] = oh;
                        *(__nv_bfloat162*)&gKl[off] = ol;
                    }
                }
            }
        }
    } else {
        __nv_bfloat16* stgh = (__nv_bfloat16*)smc;           // [128][VSP]
        __nv_bfloat16* stgl = stgh + 128 * VSP;
        #pragma unroll
        for (int nt = 0; nt < 8; nt++) {
            int ncl = wn * 64 + nt * 8 + t * 2;
            int nc = n0 + ncl;
            float b0 = bias[nc], b1 = bias[nc + 1];
            #pragma unroll
            for (int mt = 0; mt < 2; mt++) {
                #pragma unroll
                for (int half = 0; half < 2; half++) {
                    int ml = wm * 32 + mt * 16 + g + half * 8;
                    float vx = acc[mt][nt][half * 2 + 0] + b0;
                    float vy = acc[mt][nt][half * 2 + 1] + b1;
                    __nv_bfloat16 hx, lx, hy, ly;
                    split_bf16(vx, hx, lx);
                    split_bf16(vy, hy, ly);
                    stgh[ncl * VSP + ml] = hx;
                    stgh[(ncl + 1) * VSP + ml] = hy;
                    stgl[ncl * VSP + ml] = lx;
                    stgl[(ncl + 1) * VSP + ml] = ly;
                }
            }
        }
        __syncthreads();
        int b_ = m0 >> 10, sm0 = m0 & 1023;
        #pragma unroll
        for (int p = 0; p < 8; p++) {
            int idx = tid + p * 256;
            int row = idx >> 4;
            int ch = idx & 15;
            int nc = n0 + row;
            int h_ = nc >> 6, d = nc & 63;
            size_t go = ((size_t)(b_ * HH + h_) * DD + d) * SS + sm0 + ch * 8;
            *(uint4*)&gVth[go] = *(uint4*)&stgh[row * VSP + ch * 8];
            *(uint4*)&gVtl[go] = *(uint4*)&stgl[row * VSP + ch * 8];
        }
    }
}

// ---------------------------------------------------------------------------
// attn_tc: 64-query CTA, 2 CTAs/SM. Q fragments cached in registers
// (precision-neutral); P stored SPLIT (restored — hi-only failed the gate).
// Staggered E/K/V cp.async groups. grid (16, 16, 4).
// ---------------------------------------------------------------------------
#define EPITCH 72
#define ROWB 144
#define TP 136
#define SQH 0
#define SQL 9216
#define SKH 18432
#define SKL 27648
#define SVH 36864
#define SVL 46080
#define SE  55296
#define ST  73728
#define SPH 91136
#define SPL 100352
#define SW  109568
#define ASM_BYTES 113664

__global__ __launch_bounds__(256, 2) void attn_tc_kernel(float* __restrict__ out)
{
    extern __shared__ char smc[];
    uint32_t sb = smem_u32(smc);
    int tid = threadIdx.x, wid = tid >> 5, lane = tid & 31;
    int wm = wid & 3, wn = wid >> 2;
    int b = blockIdx.z, h = blockIdx.y;
    int l0 = blockIdx.x * 64;
    int bh = b * HH + h;

    const __nv_bfloat16* pQh = gQh + ((size_t)bh * SS + l0) * DD;
    const __nv_bfloat16* pQl = gQl + ((size_t)bh * SS + l0) * DD;
    const __nv_bfloat16* pKh = gKh + (size_t)bh * SS * DD;
    const __nv_bfloat16* pKl = gKl + (size_t)bh * SS * DD;
    const __nv_bfloat16* pVh = gVth + (size_t)bh * DD * SS;
    const __nv_bfloat16* pVl = gVtl + (size_t)bh * DD * SS;

    int a_row = lane & 15;
    int a_kof = (lane >> 4) * 8;
    int b_nof = (lane & 7) | ((lane >> 4) << 3);
    int b_kof = ((lane >> 3) & 1) * 8;
    int g = lane >> 2, t = lane & 3;

    auto load_k = [&](int s2) {
        int rr = s2 * 64;
        #pragma unroll
        for (int p = 0; p < 4; p++) {
            int idx = tid + p * 256;
            int arr = idx >> 9, rc = idx & 511;
            int row = rc >> 3, ch = rc & 7;
            const __nv_bfloat16* src = (arr == 0)
                ? pKh + (size_t)(rr + row) * 64 + ch * 8
                : pKl + (size_t)(rr + row) * 64 + ch * 8;
            cp16(sb + SKH + arr * 9216 + row * ROWB + ch * 16, src);
        }
    };
    auto load_v = [&](int s2) {
        int rr = s2 * 64;
        #pragma unroll
        for (int p = 0; p < 4; p++) {
            int idx = tid + p * 256;
            int arr = idx >> 9, rc = idx & 511;
            int row = rc >> 3, ch = rc & 7;
            const __nv_bfloat16* src = (arr == 0)
                ? pVh + (size_t)row * SS + rr + ch * 8
                : pVl + (size_t)row * SS + rr + ch * 8;
            cp16(sb + SVH + arr * 9216 + row * ROWB + ch * 16, src);
        }
    };
    auto load_e = [&](int s2) {
        int base = l0 - s2 * 64 + 960;
        #pragma unroll
        for (int p = 0; p < 4; p++) {
            int idx = tid + p * 256;
            int row = idx >> 3, ch = idx & 7;
            int er = base + row;
            if (er > 2046) er = 2046;
            cp16(sb + SE + row * ROWB + ch * 16, gEh + (size_t)er * 64 + ch * 8);
        }
    };

    #pragma unroll
    for (int p = 0; p < 4; p++) {
        int idx = tid + p * 256;
        int arr = idx >> 9, rc = idx & 511;
        int row = rc >> 3, ch = rc & 7;
        cp16(sb + (arr ? SQL : SQH) + row * ROWB + ch * 16,
             (arr ? pQl : pQh) + (size_t)row * 64 + ch * 8);
    }
    cp16(sb + SW + tid * 16, gWcomb + b * SS + tid * 4);
    load_e(0);
    CP_COMMIT();
    load_k(0);
    CP_COMMIT();
    load_v(0);
    CP_COMMIT();

    CP_WAIT(2);
    __syncthreads();

    // cache Q fragments (identical A-operand for bias + QK in every tile)
    uint32_t qh[4][4], ql[4][4];
    #pragma unroll
    for (int k4 = 0; k4 < 4; k4++) {
        int off = ((wm * 16 + a_row) * EPITCH + k4 * 16 + a_kof) * 2;
        ldsm_x4(qh[k4], sb + SQH + off);
        ldsm_x4(ql[k4], sb + SQL + off);
    }

    float oacc[4][4] = {};
    float rs0 = 0.f, rs1 = 0.f;
    int i0 = wm * 16 + g, i1 = i0 + 8;

    for (int s = 0; s < 16; s++) {
        int r0 = s * 64;

        // ---- phase 1: bias GEMM T[64x128] = Qh @ E_band^T ----
        {
            float tac[8][4] = {};
            #pragma unroll
            for (int k4 = 0; k4 < 4; k4++) {
                #pragma unroll
                for (int np = 0; np < 4; np++) {
                    uint32_t eb4[4];
                    ldsm_x4(eb4, sb + SE + ((wn * 64 + np * 16 + b_nof) * EPITCH + k4 * 16 + b_kof) * 2);
                    mma16816(tac[np * 2 + 0], qh[k4], &eb4[0]);
                    mma16816(tac[np * 2 + 1], qh[k4], &eb4[2]);
                }
            }
            #pragma unroll
            for (int nt = 0; nt < 8; nt++) {
                int col = wn * 64 + nt * 8 + t * 2;
                *(uint32_t*)(smc + ST + (i0 * TP + col) * 2) = pack_bf16x2(tac[nt][0], tac[nt][1]);
                *(uint32_t*)(smc + ST + (i1 * TP + col) * 2) = pack_bf16x2(tac[nt][2], tac[nt][3]);
            }
        }
        CP_WAIT(1);
        __syncthreads();
        if (s + 1 < 16) {
            load_e(s + 1);
            CP_COMMIT();
        }

        // ---- phase 2: QK^T (split precision) ----
        float sac[4][4] = {};
        #pragma unroll
        for (int k4 = 0; k4 < 4; k4++) {
            #pragma unroll
            for (int np = 0; np < 2; np++) {
                uint32_t bh4[4], bl4[4];
                int roff = ((wn * 32 + np * 16 + b_nof) * EPITCH + k4 * 16 + b_kof) * 2;
                ldsm_x4(bh4, sb + SKH + roff);
                ldsm_x4(bl4, sb + SKL + roff);
                #pragma unroll
                for (int t2 = 0; t2 < 2; t2++) {
                    float* cc = sac[np * 2 + t2];
                    mma16816(cc, qh[k4], &bh4[t2 * 2]);
                    mma16816(cc, qh[k4], &bl4[t2 * 2]);
                    mma16816(cc, ql[k4], &bh4[t2 * 2]);
                }
            }
        }

        // gather T, exp, split P
        #pragma unroll
        for (int nt = 0; nt < 4; nt++) {
            int j = wn * 32 + nt * 8 + t * 2;
            float w0 = *(const float*)(smc + SW + (r0 + j) * 4);
            float w1 = *(const float*)(smc + SW + (r0 + j + 1) * 4);
            int jj0 = i0 - j + 63;
            int jj1 = i1 - j + 63;
            float t00 = __bfloat162float(*(const __nv_bfloat16*)(smc + ST + (i0 * TP + jj0) * 2));
            float t01 = __bfloat162float(*(const __nv_bfloat16*)(smc + ST + (i0 * TP + jj0 - 1) * 2));
            float t10 = __bfloat162float(*(const __nv_bfloat16*)(smc + ST + (i1 * TP + jj1) * 2));
            float t11 = __bfloat162float(*(const __nv_bfloat16*)(smc + ST + (i1 * TP + jj1 - 1) * 2));
            float p0 = __expf((sac[nt][0] + t00) * 0.125f) * w0;
            float p1 = __expf((sac[nt][1] + t01) * 0.125f) * w1;
            float p2 = __expf((sac[nt][2] + t10) * 0.125f) * w0;
            float p3 = __expf((sac[nt][3] + t11) * 0.125f) * w1;
            rs0 += p0 + p1;
            rs1 += p2 + p3;
            __nv_bfloat162 ph0, pl0, ph1, pl1;
            split_bf16(p0, ph0.x, pl0.x);
            split_bf16(p1, ph0.y, pl0.y);
            split_bf16(p2, ph1.x, pl1.x);
            split_bf16(p3, ph1.y, pl1.y);
            *(__nv_bfloat162*)(smc + SPH + (i0 * EPITCH + j) * 2) = ph0;
            *(__nv_bfloat162*)(smc + SPL + (i0 * EPITCH + j) * 2) = pl0;
            *(__nv_bfloat162*)(smc + SPH + (i1 * EPITCH + j) * 2) = ph1;
            *(__nv_bfloat162*)(smc + SPL + (i1 * EPITCH + j) * 2) = pl1;
        }
        if (s + 1 < 16) { CP_WAIT(1); } else { CP_WAIT(0); }
        __syncthreads();
        if (s + 1 < 16) {
            load_k(s + 1);
            CP_COMMIT();
        }

        // ---- phase 3: PV (split precision) ----
        #pragma unroll
        for (int kk = 0; kk < 64; kk += 16) {
            uint32_t ph4[4], pl4[4];
            ldsm_x4(ph4, sb + SPH + ((wm * 16 + a_row) * EPITCH + kk + a_kof) * 2);
            ldsm_x4(pl4, sb + SPL + ((wm * 16 + a_row) * EPITCH + kk + a_kof) * 2);
            #pragma unroll
            for (int np = 0; np < 2; np++) {
                uint32_t bh4[4], bl4[4];
                int roff = ((wn * 32 + np * 16 + b_nof) * EPITCH + kk + b_kof) * 2;
                ldsm_x4(bh4, sb + SVH + roff);
                ldsm_x4(bl4, sb + SVL + roff);
                #pragma unroll
                for (int t2 = 0; t2 < 2; t2++) {
                    float* cc = oacc[np * 2 + t2];
                    mma16816(cc, ph4, &bh4[t2 * 2]);
                    mma16816(cc, ph4, &bl4[t2 * 2]);
                    mma16816(cc, pl4, &bh4[t2 * 2]);
                }
            }
        }
        if (s + 1 < 16) {
            CP_WAIT(1);
            __syncthreads();
            load_v(s + 1);
            CP_COMMIT();
        } else {
            __syncthreads();
        }
    }

    // ---- finalize ----
    rs0 += __shfl_xor_sync(0xFFFFFFFFu, rs0, 1);
    rs0 += __shfl_xor_sync(0xFFFFFFFFu, rs0, 2);
    rs1 += __shfl_xor_sync(0xFFFFFFFFu, rs1, 1);
    rs1 += __shfl_xor_sync(0xFFFFFFFFu, rs1, 2);

    float* red = (float*)(smc + ST);
    red[i0 * 2 + wn] = rs0;
    red[i1 * 2 + wn] = rs1;
    __syncthreads();
    float inv0 = 1.0f / (1e-8f + red[i0 * 2] + red[i0 * 2 + 1]);
    float inv1 = 1.0f / (1e-8f + red[i1 * 2] + red[i1 * 2 + 1]);

    #pragma unroll
    for (int nt = 0; nt < 4; nt++) {
        int d = wn * 32 + nt * 8 + t * 2;
        float2 o0, o1;
        o0.x = oacc[nt][0] * inv0;
        o0.y = oacc[nt][1] * inv0;
        o1.x = oacc[nt][2] * inv1;
        o1.y = oacc[nt][3] * inv1;
        *(float2*)&out[(size_t)(b * SS + l0 + i0) * HIDD + h * 64 + d] = o0;
        *(float2*)&out[(size_t)(b * SS + l0 + i1) * HIDD + h * 64 + d] = o1;
    }
}

extern "C" void kernel_launch(void* const* d_in, const int* in_sizes, int n_in,
                              void* d_out, int out_size)
{
    const float* hs    = (const float*)d_in[0];
    const float* amask = (const float*)d_in[1];
    const int*   skm   = (const int*)  d_in[2];
    const float* Wq    = (const float*)d_in[3];
    const float* bq    = (const float*)d_in[4];
    const float* Wk    = (const float*)d_in[5];
    const float* bk    = (const float*)d_in[6];
    const float* Wv    = (const float*)d_in[7];
    const float* bv    = (const float*)d_in[8];
    const float* E     = (const float*)d_in[9];
    float* out = (float*)d_out;

    cudaFuncSetAttribute(qkv_tc_kernel, cudaFuncAttributeMaxDynamicSharedMemorySize, QSM_BYTES);
    cudaFuncSetAttribute(attn_tc_kernel, cudaFuncAttributeMaxDynamicSharedMemorySize, ASM_BYTES);

    conv_all_kernel<<<7312, 256>>>(hs, Wq, Wk, Wv, E, amask, skm);
    qkv_tc_kernel<<<dim3(32, 24), 256, QSM_BYTES>>>(bq, bk, bv);
    attn_tc_kernel<<<dim3(16, 16, 4), 256, ASM_BYTES>>>(out);
}